// round 8
// baseline (speedup 1.0000x reference)
#include <cuda_runtime.h>
#include <cuda_bf16.h>
#include <cstdint>

// ---- problem constants ----
#define Bq   4
#define Tq   1024
#define Eq   512
#define Hq   8
#define HDq  64
#define NBq  5
#define VOC  32000
#define MROWS (Bq*Tq)          // 4096

// ---- scratch (device globals; no allocations allowed) ----
__device__ float g_h1 [MROWS*Eq];
__device__ float g_h2 [MROWS*Eq];
__device__ float g_kq [MROWS*1024];     // fused K|Q output
__device__ float g_mha[MROWS*Eq];
__device__ float g_wkr[NBq*Eq*Eq];
__device__ float g_wqr[NBq*Eq*Eq];
// activation hi/lo splits (bf16)
__device__ __nv_bfloat16 g_h1hi[MROWS*Eq], g_h1lo[MROWS*Eq];
__device__ __nv_bfloat16 g_hnhi[MROWS*Eq], g_hnlo[MROWS*Eq];
// weight hi/lo splits, transposed to [N][K=512] row-major
__device__ __nv_bfloat16 g_wkqhi[NBq*1024*Eq], g_wkqlo[NBq*1024*Eq];   // K|Q concat
__device__ __nv_bfloat16 g_wrhi[NBq*Eq*Eq], g_wrlo[NBq*Eq*Eq];
__device__ __nv_bfloat16 g_wmhi[NBq*Eq*Eq], g_wmlo[NBq*Eq*Eq];
__device__ __nv_bfloat16 g_pjhi[(size_t)Eq*VOC], g_pjlo[(size_t)Eq*VOC];

// ============================================================
// helpers
// ============================================================
__device__ __forceinline__ uint32_t smem_u32(const void* p) {
    uint32_t a;
    asm("{ .reg .u64 t; cvta.to.shared.u64 t, %1; cvt.u32.u64 %0, t; }"
        : "=r"(a) : "l"(p));
    return a;
}
__device__ __forceinline__ void ldsm4(uint32_t* r, uint32_t addr) {
    asm volatile("ldmatrix.sync.aligned.m8n8.x4.shared.b16 {%0,%1,%2,%3}, [%4];"
                 : "=r"(r[0]), "=r"(r[1]), "=r"(r[2]), "=r"(r[3]) : "r"(addr));
}
__device__ __forceinline__ void mma16816(float* c, const uint32_t* a, const uint32_t* b) {
    asm volatile(
        "mma.sync.aligned.m16n8k16.row.col.f32.bf16.bf16.f32 "
        "{%0,%1,%2,%3}, {%4,%5,%6,%7}, {%8,%9}, {%0,%1,%2,%3};"
        : "+f"(c[0]), "+f"(c[1]), "+f"(c[2]), "+f"(c[3])
        : "r"(a[0]), "r"(a[1]), "r"(a[2]), "r"(a[3]), "r"(b[0]), "r"(b[1]));
}
#define CPASYNC(dst, src) \
    asm volatile("cp.async.cg.shared.global [%0], [%1], 16;" :: "r"(dst), "l"(src))
#define CPCOMMIT() asm volatile("cp.async.commit_group;" ::: "memory")
#define CPWAIT2()  asm volatile("cp.async.wait_group 2;" ::: "memory")

__device__ __forceinline__ uint32_t pack_hi2(float x, float y) {
    __nv_bfloat16 hx = __float2bfloat16(x), hy = __float2bfloat16(y);
    return (uint32_t)__bfloat16_as_ushort(hx) | ((uint32_t)__bfloat16_as_ushort(hy) << 16);
}
__device__ __forceinline__ uint32_t pack_lo2(float x, float y) {
    __nv_bfloat16 hx = __float2bfloat16(x), hy = __float2bfloat16(y);
    __nv_bfloat16 lx = __float2bfloat16(x - __bfloat162float(hx));
    __nv_bfloat16 ly = __float2bfloat16(y - __bfloat162float(hy));
    return (uint32_t)__bfloat16_as_ushort(lx) | ((uint32_t)__bfloat16_as_ushort(ly) << 16);
}

// ============================================================
// repack Wk/Wq: [NB,H,E,HD] -> [NB,E(k),H*HD(n)]
// ============================================================
__global__ void repack_kernel(const float* __restrict__ in, float* __restrict__ out)
{
    int tid = blockIdx.x * blockDim.x + threadIdx.x;
    if (tid >= NBq * Hq * Eq * 16) return;
    int o4 = tid & 15;
    int e  = (tid >> 4) & 511;
    int h  = (tid >> 13) & 7;
    int i  = tid >> 16;
    float4 v = *(const float4*)(in  + ((((size_t)i*Hq + h)*Eq + e)*HDq + o4*4));
    *(float4*)(out + (((size_t)i*Eq + e)*Eq + h*HDq + o4*4)) = v;
}

// ============================================================
// weight transpose + hi/lo split: W[K=512][Nfull] -> hi/lo [Nfull][512]
// grid (Nfull/32, 16, zCount), 256 threads, 32x32 tiles
// ============================================================
__global__ __launch_bounds__(256) void tsplit_kernel(
    const float* __restrict__ W, long long wChunk, int Nfull,
    __nv_bfloat16* __restrict__ hi, __nv_bfloat16* __restrict__ lo,
    long long oChunk)
{
    __shared__ float t[32][33];
    const float* w = W + (long long)blockIdx.z * wChunk;
    __nv_bfloat16* oh = hi + (long long)blockIdx.z * oChunk;
    __nv_bfloat16* ol = lo + (long long)blockIdx.z * oChunk;
    int n0 = blockIdx.x * 32, k0 = blockIdx.y * 32;
    int lw = threadIdx.x >> 5, lc = threadIdx.x & 31;
    #pragma unroll
    for (int i = 0; i < 4; i++) {
        int kk = lw + i * 8;
        t[kk][lc] = w[(size_t)(k0 + kk) * Nfull + n0 + lc];
    }
    __syncthreads();
    #pragma unroll
    for (int i = 0; i < 4; i++) {
        int nn = lw + i * 8;
        float v = t[lc][nn];
        __nv_bfloat16 h = __float2bfloat16(v);
        __nv_bfloat16 l = __float2bfloat16(v - __bfloat162float(h));
        size_t o = (size_t)(n0 + nn) * 512 + k0 + lc;
        oh[o] = h; ol[o] = l;
    }
}

// ============================================================
// embedding: h = tok_emb[x] + pos_emb ; also write hi/lo split
// ============================================================
__global__ void embed_kernel(const int* __restrict__ x,
                             const float* __restrict__ tok,
                             const float* __restrict__ pos,
                             float* __restrict__ h,
                             __nv_bfloat16* __restrict__ ohi,
                             __nv_bfloat16* __restrict__ olo)
{
    int row = blockIdx.x;
    int t   = row & (Tq - 1);
    int idx = x[row];
    int tid = threadIdx.x;
    float4 a = ((const float4*)(tok + (size_t)idx * Eq))[tid];
    float4 p = ((const float4*)(pos + (size_t)t   * Eq))[tid];
    float4 o; o.x = a.x+p.x; o.y = a.y+p.y; o.z = a.z+p.z; o.w = a.w+p.w;
    ((float4*)(h + (size_t)row * Eq))[tid] = o;
    size_t e = (size_t)row * Eq + tid * 4;
    *(uint2*)(ohi + e) = make_uint2(pack_hi2(o.x, o.y), pack_hi2(o.z, o.w));
    *(uint2*)(olo + e) = make_uint2(pack_lo2(o.x, o.y), pack_lo2(o.z, o.w));
}

// ============================================================
// layernorm -> hi/lo bf16 split (GEMM A operand format)
// ============================================================
__global__ void ln_split_kernel(const float* __restrict__ in,
                                const float* __restrict__ g,
                                const float* __restrict__ b,
                                __nv_bfloat16* __restrict__ ohi,
                                __nv_bfloat16* __restrict__ olo)
{
    int row = blockIdx.x, tid = threadIdx.x;
    float4 v = ((const float4*)(in + (size_t)row * Eq))[tid];
    float s  = v.x + v.y + v.z + v.w;
    float sq = v.x*v.x + v.y*v.y + v.z*v.z + v.w*v.w;
    #pragma unroll
    for (int o = 16; o; o >>= 1) {
        s  += __shfl_xor_sync(0xffffffffu, s,  o);
        sq += __shfl_xor_sync(0xffffffffu, sq, o);
    }
    __shared__ float sm1[4], sm2[4];
    int wid = tid >> 5, lane = tid & 31;
    if (lane == 0) { sm1[wid] = s; sm2[wid] = sq; }
    __syncthreads();
    s  = sm1[0] + sm1[1] + sm1[2] + sm1[3];
    sq = sm2[0] + sm2[1] + sm2[2] + sm2[3];
    float mu   = s * (1.0f / Eq);
    float var  = sq * (1.0f / Eq) - mu * mu;
    float rstd = rsqrtf(var + 1e-5f);
    float4 gv = ((const float4*)g)[tid];
    float4 bv = ((const float4*)b)[tid];
    float4 o;
    o.x = (v.x - mu) * rstd * gv.x + bv.x;
    o.y = (v.y - mu) * rstd * gv.y + bv.y;
    o.z = (v.z - mu) * rstd * gv.z + bv.z;
    o.w = (v.w - mu) * rstd * gv.w + bv.w;
    size_t e = (size_t)row * Eq + tid * 4;
    *(uint2*)(ohi + e) = make_uint2(pack_hi2(o.x, o.y), pack_hi2(o.z, o.w));
    *(uint2*)(olo + e) = make_uint2(pack_lo2(o.x, o.y), pack_lo2(o.z, o.w));
}

// ============================================================
// bf16x3 HMMA GEMM v2: C[M,N] = A[M,512] @ W[512,N]
// A hi/lo bf16 [M][512]; B = W^T hi/lo bf16 [N][512].
// acc += Ahi*Bhi + Ahi*Blo + Alo*Bhi  (fp32 accumulate)
// 128x128x32 tile, 512 thr = 16 warps (4m x 4n), warp 32x32,
// 4-stage cp.async, one barrier per stage, pitch-40 smem.
// ============================================================
#define PITCH 40
#define MATB   (128 * PITCH * 2)        // 10240 bytes per matrix tile
#define STAGEB (4 * MATB)               // 40960
#define SMEMB  (4 * STAGEB)             // 163840

template<bool BIAS, bool RELU, bool RESID, bool OSPLIT>
__global__ __launch_bounds__(512) void hgemm(
    const __nv_bfloat16* __restrict__ Ahi, const __nv_bfloat16* __restrict__ Alo,
    const __nv_bfloat16* __restrict__ Bhi, const __nv_bfloat16* __restrict__ Blo,
    const float* __restrict__ bias, const float* __restrict__ resid,
    float* __restrict__ C,
    __nv_bfloat16* __restrict__ Ohi, __nv_bfloat16* __restrict__ Olo,
    int N)
{
    extern __shared__ char dsm[];
    const uint32_t sb = smem_u32(dsm);
    const int tid = threadIdx.x;
    const int wid = tid >> 5, lane = tid & 31;
    const int wm = wid & 3, wn = wid >> 2;
    const int m0 = blockIdx.x * 128, n0 = blockIdx.y * 128;

    // ldmatrix per-lane smem offsets
    uint32_t aOff[2], bOff[2];
    {
        int ml = lane >> 3, r8 = lane & 7;
        int ar = (ml & 1) * 8 + r8;
        int ac = (ml >> 1) * 8;
        #pragma unroll
        for (int mi = 0; mi < 2; mi++)
            aOff[mi] = (uint32_t)(((wm * 32 + mi * 16 + ar) * PITCH + ac) * 2);
        int br = (ml >> 1) * 8 + r8;
        int bc = (ml & 1) * 8;
        #pragma unroll
        for (int j = 0; j < 2; j++)
            bOff[j] = (uint32_t)(((wn * 32 + j * 16 + br) * PITCH + bc) * 2);
    }

    // per stage: each thread moves one 16B chunk per matrix
    const int lrow = tid >> 2, lc4 = tid & 3;
    auto loadStage = [&](int s) {
        uint32_t base = sb + (s & 3) * STAGEB;
        uint32_t doff = (uint32_t)((lrow * PITCH + lc4 * 8) * 2);
        size_t ga = (size_t)(m0 + lrow) * 512 + s * 32 + lc4 * 8;
        size_t gb = (size_t)(n0 + lrow) * 512 + s * 32 + lc4 * 8;
        CPASYNC(base +            doff, Ahi + ga);
        CPASYNC(base + MATB     + doff, Alo + ga);
        CPASYNC(base + 2 * MATB + doff, Bhi + gb);
        CPASYNC(base + 3 * MATB + doff, Blo + gb);
    };

    float acc[2][4][4];
    #pragma unroll
    for (int i = 0; i < 2; i++)
        #pragma unroll
        for (int j = 0; j < 4; j++)
            #pragma unroll
            for (int q = 0; q < 4; q++) acc[i][j][q] = 0.0f;

    loadStage(0); CPCOMMIT();
    loadStage(1); CPCOMMIT();
    loadStage(2); CPCOMMIT();

    for (int s = 0; s < 16; s++) {
        CPWAIT2();                       // stage s complete
        __syncthreads();                 // visible to all; all warps done with buf (s-1)&3
        if (s + 3 < 16) { loadStage(s + 3); CPCOMMIT(); }
        uint32_t base = sb + (s & 3) * STAGEB;
        #pragma unroll
        for (int kk = 0; kk < 2; kk++) {
            uint32_t ah[8], al[8], bh[8], bl[8];
            #pragma unroll
            for (int mi = 0; mi < 2; mi++) {
                ldsm4(ah + mi * 4, base +        aOff[mi] + kk * 32);
                ldsm4(al + mi * 4, base + MATB + aOff[mi] + kk * 32);
            }
            #pragma unroll
            for (int j = 0; j < 2; j++) {
                ldsm4(bh + j * 4, base + 2 * MATB + bOff[j] + kk * 32);
                ldsm4(bl + j * 4, base + 3 * MATB + bOff[j] + kk * 32);
            }
            #pragma unroll
            for (int mi = 0; mi < 2; mi++)
                #pragma unroll
                for (int ni = 0; ni < 4; ni++) {
                    mma16816(acc[mi][ni], ah + mi * 4, bh + ni * 2);
                    mma16816(acc[mi][ni], ah + mi * 4, bl + ni * 2);
                    mma16816(acc[mi][ni], al + mi * 4, bh + ni * 2);
                }
        }
        __syncthreads();                 // done reading buf s before next-iter load of (s+4)&3
    }

    // epilogue: d0,d1=(r,c..c+1), d2,d3=(r+8,c..c+1)
    const int r  = lane >> 2;
    const int cp = (lane & 3) * 2;
    #pragma unroll
    for (int mi = 0; mi < 2; mi++) {
        #pragma unroll
        for (int ni = 0; ni < 4; ni++) {
            int col  = n0 + wn * 32 + ni * 8 + cp;
            int row0 = m0 + wm * 32 + mi * 16 + r;
            #pragma unroll
            for (int hh = 0; hh < 2; hh++) {
                int row = row0 + hh * 8;
                float v0 = acc[mi][ni][hh * 2];
                float v1 = acc[mi][ni][hh * 2 + 1];
                if (BIAS) { v0 += bias[col]; v1 += bias[col + 1]; }
                if (RELU) { v0 = fmaxf(v0, 0.0f); v1 = fmaxf(v1, 0.0f); }
                if (RESID) {
                    float2 rr = *(const float2*)(resid + (size_t)row * N + col);
                    v0 += rr.x; v1 += rr.y;
                }
                *(float2*)(C + (size_t)row * N + col) = make_float2(v0, v1);
                if (OSPLIT) {
                    *(uint32_t*)(Ohi + (size_t)row * N + col) = pack_hi2(v0, v1);
                    *(uint32_t*)(Olo + (size_t)row * N + col) = pack_lo2(v0, v1);
                }
            }
        }
    }
}

// ============================================================
// fused causal attention (reference quirks: scores = k@q^T,
// v == q, scale = E^-0.5). K and Q packed in kq [M][1024]
// (K cols 0..511, Q cols 512..1023). O -> [M][512].
// grid (T/8, B*H), 8 warps; warp = query row t.
// ============================================================
__global__ __launch_bounds__(256) void attn_kernel(
    const float* __restrict__ KQ, float* __restrict__ O)
{
    __shared__ float qs[128][69];                 // pad 69: conflict-free both ways
    int bh = blockIdx.y;
    int b = bh >> 3, h = bh & 7;
    int wid = threadIdx.x >> 5, lane = threadIdx.x & 31;
    int t = blockIdx.x * 8 + wid;
    const float scale = 0.044194173824159216f;    // 512^-0.5
    size_t kbase = ((size_t)(b * Tq + t)) * 1024 + h * HDq;
    float k0 = KQ[kbase + lane] * scale;
    float k1 = KQ[kbase + lane + 32] * scale;
    float m = -1e30f, l = 0.0f, a0 = 0.0f, a1 = 0.0f;
    int tmax = blockIdx.x * 8 + 7;

    for (int s0 = 0; s0 <= tmax; s0 += 128) {
        #pragma unroll
        for (int it = 0; it < 8; it++) {
            int idx = it * 256 + threadIdx.x;
            int rr = idx >> 4, d4 = (idx & 15) * 4;
            float4 v = *(const float4*)&KQ[((size_t)(b * Tq + s0 + rr)) * 1024 + 512 + h * HDq + d4];
            qs[rr][d4] = v.x; qs[rr][d4+1] = v.y; qs[rr][d4+2] = v.z; qs[rr][d4+3] = v.w;
        }
        __syncthreads();

        int send = min(127, t - s0);
        int nch = (send >> 5) + 1;
        for (int c = 0; c < nch; c++) {
            int sb32 = c * 32;
            const float* qrow = qs[sb32 + lane];
            float p = 0.0f;
            #pragma unroll
            for (int d = 0; d < 32; d++)
                p = fmaf(__shfl_sync(0xffffffffu, k0, d), qrow[d], p);
            #pragma unroll
            for (int d = 0; d < 32; d++)
                p = fmaf(__shfl_sync(0xffffffffu, k1, d), qrow[d + 32], p);
            if (sb32 + lane > send) p = -1e30f;           // causal mask
            float cm = p;
            #pragma unroll
            for (int o = 16; o; o >>= 1)
                cm = fmaxf(cm, __shfl_xor_sync(0xffffffffu, cm, o));
            float mn = fmaxf(m, cm);
            float alpha = __expf(m - mn);
            float w = __expf(p - mn);
            float sw = w;
            #pragma unroll
            for (int o = 16; o; o >>= 1)
                sw += __shfl_xor_sync(0xffffffffu, sw, o);
            l = fmaf(l, alpha, sw);
            a0 *= alpha; a1 *= alpha;
            #pragma unroll 8
            for (int s2 = 0; s2 < 32; s2++) {
                float ws = __shfl_sync(0xffffffffu, w, s2);
                a0 = fmaf(ws, qs[sb32 + s2][lane], a0);
                a1 = fmaf(ws, qs[sb32 + s2][lane + 32], a1);
            }
            m = mn;
        }
        __syncthreads();
    }
    float inv = 1.0f / l;
    size_t obase = ((size_t)(b * Tq + t)) * Eq + h * HDq;
    O[obase + lane]      = a0 * inv;
    O[obase + lane + 32] = a1 * inv;
}

// ============================================================
// launch
// ============================================================
extern "C" void kernel_launch(void* const* d_in, const int* in_sizes, int n_in,
                              void* d_out, int out_size)
{
    const int*   x     = (const int*)  d_in[0];
    const float* tok   = (const float*)d_in[1];
    const float* pos   = (const float*)d_in[2];
    const float* Wk    = (const float*)d_in[3];
    const float* Wq    = (const float*)d_in[4];
    const float* Wres  = (const float*)d_in[5];
    const float* ln1g  = (const float*)d_in[6];
    const float* ln1b  = (const float*)d_in[7];
    const float* mlpW  = (const float*)d_in[8];
    const float* mlpb  = (const float*)d_in[9];
    const float* ln2g  = (const float*)d_in[10];
    const float* ln2b  = (const float*)d_in[11];
    const float* lnfg  = (const float*)d_in[12];
    const float* lnfb  = (const float*)d_in[13];
    const float* projW = (const float*)d_in[14];
    const float* projb = (const float*)d_in[15];
    float* out = (float*)d_out;

    float *h1, *h2, *kq, *mha, *wkr, *wqr;
    __nv_bfloat16 *h1hi, *h1lo, *hnhi, *hnlo;
    __nv_bfloat16 *wkqhi, *wkqlo, *wrhi, *wrlo, *wmhi, *wmlo, *pjhi, *pjlo;
    cudaGetSymbolAddress((void**)&h1,  g_h1);
    cudaGetSymbolAddress((void**)&h2,  g_h2);
    cudaGetSymbolAddress((void**)&kq,  g_kq);
    cudaGetSymbolAddress((void**)&mha, g_mha);
    cudaGetSymbolAddress((void**)&wkr, g_wkr);
    cudaGetSymbolAddress((void**)&wqr, g_wqr);
    cudaGetSymbolAddress((void**)&h1hi, g_h1hi);
    cudaGetSymbolAddress((void**)&h1lo, g_h1lo);
    cudaGetSymbolAddress((void**)&hnhi, g_hnhi);
    cudaGetSymbolAddress((void**)&hnlo, g_hnlo);
    cudaGetSymbolAddress((void**)&wkqhi, g_wkqhi);
    cudaGetSymbolAddress((void**)&wkqlo, g_wkqlo);
    cudaGetSymbolAddress((void**)&wrhi, g_wrhi);
    cudaGetSymbolAddress((void**)&wrlo, g_wrlo);
    cudaGetSymbolAddress((void**)&wmhi, g_wmhi);
    cudaGetSymbolAddress((void**)&wmlo, g_wmlo);
    cudaGetSymbolAddress((void**)&pjhi, g_pjhi);
    cudaGetSymbolAddress((void**)&pjlo, g_pjlo);

    cudaFuncSetAttribute(hgemm<false,false,false,false>, cudaFuncAttributeMaxDynamicSharedMemorySize, SMEMB);
    cudaFuncSetAttribute(hgemm<false,false,true,false>,  cudaFuncAttributeMaxDynamicSharedMemorySize, SMEMB);
    cudaFuncSetAttribute(hgemm<true,true,true,true>,     cudaFuncAttributeMaxDynamicSharedMemorySize, SMEMB);
    cudaFuncSetAttribute(hgemm<true,false,false,false>,  cudaFuncAttributeMaxDynamicSharedMemorySize, SMEMB);

    // ---- weight prep ----
    repack_kernel<<<1280, 256>>>(Wk, wkr);
    repack_kernel<<<1280, 256>>>(Wq, wqr);
    const long long EC = (long long)Eq * Eq;
    const long long KQC = (long long)1024 * Eq;
    // K half -> rows 0..511, Q half -> rows 512..1023 of each [1024][512] chunk
    tsplit_kernel<<<dim3(16, 16, NBq), 256>>>(wkr,  EC, Eq,  wkqhi,            wkqlo,            KQC);
    tsplit_kernel<<<dim3(16, 16, NBq), 256>>>(wqr,  EC, Eq,  wkqhi + Eq * 512, wkqlo + Eq * 512, KQC);
    tsplit_kernel<<<dim3(16, 16, NBq), 256>>>(Wres, EC, Eq,  wrhi, wrlo, EC);
    tsplit_kernel<<<dim3(16, 16, NBq), 256>>>(mlpW, EC, Eq,  wmhi, wmlo, EC);
    tsplit_kernel<<<dim3(1000, 16, 1), 256>>>(projW, 0, VOC, pjhi, pjlo, 0);

    embed_kernel<<<MROWS, 128>>>(x, tok, pos, h1, h1hi, h1lo);

    dim3 gkq(MROWS / 128, 1024 / 128);           // 32 x 8 = 256 CTAs
    dim3 ge (MROWS / 128, Eq / 128);             // 32 x 4 = 128 CTAs
    for (int i = 0; i < NBq; i++) {
        const size_t wo  = (size_t)i * Eq * Eq;
        const size_t wokq = (size_t)i * 1024 * Eq;
        ln_split_kernel<<<MROWS, 128>>>(h1, ln1g + i * Eq, ln1b + i * Eq, hnhi, hnlo);
        hgemm<false,false,false,false><<<gkq, 512, SMEMB>>>(
            hnhi, hnlo, wkqhi + wokq, wkqlo + wokq, nullptr, nullptr, kq, nullptr, nullptr, 1024);
        attn_kernel<<<dim3(Tq / 8, Bq * Hq), 256>>>(kq, mha);
        hgemm<false,false,true,false><<<ge, 512, SMEMB>>>(
            h1hi, h1lo, wrhi + wo, wrlo + wo, nullptr, mha, h2, nullptr, nullptr, Eq);
        ln_split_kernel<<<MROWS, 128>>>(h2, ln2g + i * Eq, ln2b + i * Eq, hnhi, hnlo);
        hgemm<true,true,true,true><<<ge, 512, SMEMB>>>(
            hnhi, hnlo, wmhi + wo, wmlo + wo, mlpb + i * Eq, h2, h1, h1hi, h1lo, Eq);
    }

    ln_split_kernel<<<MROWS, 128>>>(h1, lnfg, lnfb, hnhi, hnlo);
    hgemm<true,false,false,false><<<dim3(MROWS / 128, VOC / 128), 512, SMEMB>>>(
        hnhi, hnlo, pjhi, pjlo, projb, nullptr, out, nullptr, nullptr, VOC);
}

// round 9
// speedup vs baseline: 1.0070x; 1.0070x over previous
#include <cuda_runtime.h>
#include <cuda_bf16.h>
#include <cstdint>

// ---- problem constants ----
#define Bq   4
#define Tq   1024
#define Eq   512
#define Hq   8
#define HDq  64
#define NBq  5
#define VOC  32000
#define MROWS (Bq*Tq)          // 4096

// ---- scratch (device globals; no allocations allowed) ----
__device__ float g_h1 [MROWS*Eq];
__device__ float g_h2 [MROWS*Eq];
__device__ float g_kq [MROWS*1024];     // fused K|Q output
__device__ float g_mha[MROWS*Eq];
// activation hi/lo splits (bf16)
__device__ __nv_bfloat16 g_h1hi[MROWS*Eq], g_h1lo[MROWS*Eq];
__device__ __nv_bfloat16 g_hnhi[MROWS*Eq], g_hnlo[MROWS*Eq];
// weight hi/lo splits, transposed to [N][K=512] row-major
__device__ __nv_bfloat16 g_wkqhi[NBq*1024*Eq], g_wkqlo[NBq*1024*Eq];   // K|Q concat
__device__ __nv_bfloat16 g_wrhi[NBq*Eq*Eq], g_wrlo[NBq*Eq*Eq];
__device__ __nv_bfloat16 g_wmhi[NBq*Eq*Eq], g_wmlo[NBq*Eq*Eq];
__device__ __nv_bfloat16 g_pjhi[(size_t)Eq*VOC], g_pjlo[(size_t)Eq*VOC];

// ============================================================
// helpers
// ============================================================
__device__ __forceinline__ uint32_t smem_u32(const void* p) {
    uint32_t a;
    asm("{ .reg .u64 t; cvta.to.shared.u64 t, %1; cvt.u32.u64 %0, t; }"
        : "=r"(a) : "l"(p));
    return a;
}
__device__ __forceinline__ void ldsm4(uint32_t* r, uint32_t addr) {
    asm volatile("ldmatrix.sync.aligned.m8n8.x4.shared.b16 {%0,%1,%2,%3}, [%4];"
                 : "=r"(r[0]), "=r"(r[1]), "=r"(r[2]), "=r"(r[3]) : "r"(addr));
}
__device__ __forceinline__ void mma16816(float* c, const uint32_t* a, const uint32_t* b) {
    asm volatile(
        "mma.sync.aligned.m16n8k16.row.col.f32.bf16.bf16.f32 "
        "{%0,%1,%2,%3}, {%4,%5,%6,%7}, {%8,%9}, {%0,%1,%2,%3};"
        : "+f"(c[0]), "+f"(c[1]), "+f"(c[2]), "+f"(c[3])
        : "r"(a[0]), "r"(a[1]), "r"(a[2]), "r"(a[3]), "r"(b[0]), "r"(b[1]));
}
#define CPASYNC(dst, src) \
    asm volatile("cp.async.cg.shared.global [%0], [%1], 16;" :: "r"(dst), "l"(src))
#define CPCOMMIT() asm volatile("cp.async.commit_group;" ::: "memory")
#define CPWAIT2()  asm volatile("cp.async.wait_group 2;" ::: "memory")

__device__ __forceinline__ uint32_t pack_hi2(float x, float y) {
    __nv_bfloat16 hx = __float2bfloat16(x), hy = __float2bfloat16(y);
    return (uint32_t)__bfloat16_as_ushort(hx) | ((uint32_t)__bfloat16_as_ushort(hy) << 16);
}
__device__ __forceinline__ uint32_t pack_lo2(float x, float y) {
    __nv_bfloat16 hx = __float2bfloat16(x), hy = __float2bfloat16(y);
    __nv_bfloat16 lx = __float2bfloat16(x - __bfloat162float(hx));
    __nv_bfloat16 ly = __float2bfloat16(y - __bfloat162float(hy));
    return (uint32_t)__bfloat16_as_ushort(lx) | ((uint32_t)__bfloat16_as_ushort(ly) << 16);
}

// ============================================================
// prep_all: ALL weight prep in ONE launch.
// Each block transposes one 32x32 tile and writes bf16 hi/lo to the
// [N][512] blobs. Job decoded from blockIdx.x:
//   [0,1280)      Wk  [NB,H,E,HD] -> kq rows [0,512)    of [NB][1024][512]
//   [1280,2560)   Wq  ->            kq rows [512,1024)
//   [2560,3840)   Wres [NB,E,E]  -> wr [NB][512][512]
//   [3840,5120)   mlpW           -> wm
//   [5120,21120)  projW [512,VOC]-> pj [VOC][512]
// ============================================================
__global__ __launch_bounds__(256) void prep_all(
    const float* __restrict__ Wk, const float* __restrict__ Wq,
    const float* __restrict__ Wres, const float* __restrict__ mlpW,
    const float* __restrict__ projW,
    __nv_bfloat16* __restrict__ kqhi, __nv_bfloat16* __restrict__ kqlo,
    __nv_bfloat16* __restrict__ rhi,  __nv_bfloat16* __restrict__ rlo,
    __nv_bfloat16* __restrict__ mhi,  __nv_bfloat16* __restrict__ mlo,
    __nv_bfloat16* __restrict__ phi,  __nv_bfloat16* __restrict__ plo)
{
    __shared__ float t[32][33];
    int j = blockIdx.x;
    const float* src; int rs; size_t ibase, obase;
    __nv_bfloat16 *oh, *ol;

    if (j < 2560) {                       // Wk / Wq: [nbh][e][hd] -> [nb][1024][512]
        int q = (j >= 1280);
        int u = j - q * 1280;
        int nbh = u >> 5, tt = u & 31;
        int et = tt & 15, ht = tt >> 4;   // e tile (16), hd tile (2)
        int nb = nbh >> 3, h = nbh & 7;
        int e0 = et * 32, hd0 = ht * 32;
        src   = q ? Wq : Wk;
        rs    = HDq;
        ibase = ((size_t)nbh * Eq + e0) * HDq + hd0;              // row=e, col=hd
        obase = ((size_t)nb * 1024 + q * 512 + h * HDq + hd0) * 512 + e0;
        oh = kqhi; ol = kqlo;
    } else if (j < 5120) {                // Wres / mlpW: [nb][k][n] -> [nb][512][512]
        int q = (j >= 3840);
        int u = j - 2560 - q * 1280;
        int nb = u >> 8, tt = u & 255;
        int nt = tt & 15, kt = tt >> 4;
        int n0 = nt * 32, k0 = kt * 32;
        src   = q ? mlpW : Wres;
        rs    = Eq;
        ibase = ((size_t)nb * Eq + k0) * Eq + n0;                 // row=k, col=n
        obase = ((size_t)nb * Eq + n0) * Eq + k0;
        oh = q ? mhi : rhi; ol = q ? mlo : rlo;
    } else {                              // projW [512][VOC] -> [VOC][512]
        int u = j - 5120;
        int nt = u % 1000, kt = u / 1000;
        int n0 = nt * 32, k0 = kt * 32;
        src   = projW;
        rs    = VOC;
        ibase = (size_t)k0 * VOC + n0;
        obase = (size_t)n0 * 512 + k0;
        oh = phi; ol = plo;
    }

    int lw = threadIdx.x >> 5, lc = threadIdx.x & 31;
    #pragma unroll
    for (int i = 0; i < 4; i++) {
        int r = lw + i * 8;
        t[r][lc] = src[ibase + (size_t)r * rs + lc];
    }
    __syncthreads();
    #pragma unroll
    for (int i = 0; i < 4; i++) {
        int c = lw + i * 8;               // output row offset (input col)
        float v = t[lc][c];
        __nv_bfloat16 h = __float2bfloat16(v);
        __nv_bfloat16 l = __float2bfloat16(v - __bfloat162float(h));
        size_t o = obase + (size_t)c * 512 + lc;
        oh[o] = h; ol[o] = l;
    }
}

// ============================================================
// embedding: h = tok_emb[x] + pos_emb ; also write hi/lo split
// ============================================================
__global__ void embed_kernel(const int* __restrict__ x,
                             const float* __restrict__ tok,
                             const float* __restrict__ pos,
                             float* __restrict__ h,
                             __nv_bfloat16* __restrict__ ohi,
                             __nv_bfloat16* __restrict__ olo)
{
    int row = blockIdx.x;
    int t   = row & (Tq - 1);
    int idx = x[row];
    int tid = threadIdx.x;
    float4 a = ((const float4*)(tok + (size_t)idx * Eq))[tid];
    float4 p = ((const float4*)(pos + (size_t)t   * Eq))[tid];
    float4 o; o.x = a.x+p.x; o.y = a.y+p.y; o.z = a.z+p.z; o.w = a.w+p.w;
    ((float4*)(h + (size_t)row * Eq))[tid] = o;
    size_t e = (size_t)row * Eq + tid * 4;
    *(uint2*)(ohi + e) = make_uint2(pack_hi2(o.x, o.y), pack_hi2(o.z, o.w));
    *(uint2*)(olo + e) = make_uint2(pack_lo2(o.x, o.y), pack_lo2(o.z, o.w));
}

// ============================================================
// layernorm -> hi/lo bf16 split
// ============================================================
__global__ void ln_split_kernel(const float* __restrict__ in,
                                const float* __restrict__ g,
                                const float* __restrict__ b,
                                __nv_bfloat16* __restrict__ ohi,
                                __nv_bfloat16* __restrict__ olo)
{
    int row = blockIdx.x, tid = threadIdx.x;
    float4 v = ((const float4*)(in + (size_t)row * Eq))[tid];
    float s  = v.x + v.y + v.z + v.w;
    float sq = v.x*v.x + v.y*v.y + v.z*v.z + v.w*v.w;
    #pragma unroll
    for (int o = 16; o; o >>= 1) {
        s  += __shfl_xor_sync(0xffffffffu, s,  o);
        sq += __shfl_xor_sync(0xffffffffu, sq, o);
    }
    __shared__ float sm1[4], sm2[4];
    int wid = tid >> 5, lane = tid & 31;
    if (lane == 0) { sm1[wid] = s; sm2[wid] = sq; }
    __syncthreads();
    s  = sm1[0] + sm1[1] + sm1[2] + sm1[3];
    sq = sm2[0] + sm2[1] + sm2[2] + sm2[3];
    float mu   = s * (1.0f / Eq);
    float var  = sq * (1.0f / Eq) - mu * mu;
    float rstd = rsqrtf(var + 1e-5f);
    float4 gv = ((const float4*)g)[tid];
    float4 bv = ((const float4*)b)[tid];
    float4 o;
    o.x = (v.x - mu) * rstd * gv.x + bv.x;
    o.y = (v.y - mu) * rstd * gv.y + bv.y;
    o.z = (v.z - mu) * rstd * gv.z + bv.z;
    o.w = (v.w - mu) * rstd * gv.w + bv.w;
    size_t e = (size_t)row * Eq + tid * 4;
    *(uint2*)(ohi + e) = make_uint2(pack_hi2(o.x, o.y), pack_hi2(o.z, o.w));
    *(uint2*)(olo + e) = make_uint2(pack_lo2(o.x, o.y), pack_lo2(o.z, o.w));
}

// ============================================================
// bf16x3 HMMA GEMM: C[M,N] = A[M,512] @ W[512,N]
// A hi/lo bf16 [M][512]; B = W^T hi/lo bf16 [N][512].
// acc += Ahi*Bhi + Ahi*Blo + Alo*Bhi  (fp32 accumulate)
// 128x128x32 tile, 256 thr = 8 warps (2m x 4n), warp 64x32,
// 4-stage cp.async, ONE barrier per stage (cutlass ordering),
// pitch-40 smem (ldmatrix conflict-free).
// ============================================================
#define PITCH 40
#define MATB   (128 * PITCH * 2)        // 10240 bytes per matrix tile
#define STAGEB (4 * MATB)               // 40960
#define SMEMB  (4 * STAGEB)             // 163840

template<bool BIAS, bool RELU, bool RESID, bool OSPLIT>
__global__ __launch_bounds__(256) void hgemm(
    const __nv_bfloat16* __restrict__ Ahi, const __nv_bfloat16* __restrict__ Alo,
    const __nv_bfloat16* __restrict__ Bhi, const __nv_bfloat16* __restrict__ Blo,
    const float* __restrict__ bias, const float* __restrict__ resid,
    float* __restrict__ C,
    __nv_bfloat16* __restrict__ Ohi, __nv_bfloat16* __restrict__ Olo,
    int N)
{
    extern __shared__ char dsm[];
    const uint32_t sb = smem_u32(dsm);
    const int tid = threadIdx.x;
    const int wid = tid >> 5, lane = tid & 31;
    const int wm = wid & 1, wn = wid >> 1;
    const int m0 = blockIdx.x * 128, n0 = blockIdx.y * 128;

    // ldmatrix per-lane smem offsets (warp tile 64m x 32n)
    uint32_t aOff[4], bOff[2];
    {
        int ml = lane >> 3, r8 = lane & 7;
        int ar = (ml & 1) * 8 + r8;
        int ac = (ml >> 1) * 8;
        #pragma unroll
        for (int mi = 0; mi < 4; mi++)
            aOff[mi] = (uint32_t)(((wm * 64 + mi * 16 + ar) * PITCH + ac) * 2);
        int br = (ml >> 1) * 8 + r8;
        int bc = (ml & 1) * 8;
        #pragma unroll
        for (int j = 0; j < 2; j++)
            bOff[j] = (uint32_t)(((wn * 32 + j * 16 + br) * PITCH + bc) * 2);
    }

    auto loadStage = [&](int s) {
        uint32_t base = sb + (s & 3) * STAGEB;
        #pragma unroll
        for (int i = 0; i < 2; i++) {
            int idx = tid + i * 256;
            int row = idx >> 2, c4 = idx & 3;
            uint32_t doff = (uint32_t)((row * PITCH + c4 * 8) * 2);
            size_t ga = (size_t)(m0 + row) * 512 + s * 32 + c4 * 8;
            size_t gb = (size_t)(n0 + row) * 512 + s * 32 + c4 * 8;
            CPASYNC(base +            doff, Ahi + ga);
            CPASYNC(base + MATB     + doff, Alo + ga);
            CPASYNC(base + 2 * MATB + doff, Bhi + gb);
            CPASYNC(base + 3 * MATB + doff, Blo + gb);
        }
    };

    float acc[4][4][4];
    #pragma unroll
    for (int i = 0; i < 4; i++)
        #pragma unroll
        for (int j = 0; j < 4; j++)
            #pragma unroll
            for (int q = 0; q < 4; q++) acc[i][j][q] = 0.0f;

    loadStage(0); CPCOMMIT();
    loadStage(1); CPCOMMIT();
    loadStage(2); CPCOMMIT();

    for (int s = 0; s < 16; s++) {
        CPWAIT2();              // stage s complete (<=2 groups outstanding)
        __syncthreads();        // data visible; all warps finished buffer (s+3)&3
        if (s + 3 < 16) { loadStage(s + 3); CPCOMMIT(); }
        uint32_t base = sb + (s & 3) * STAGEB;
        #pragma unroll
        for (int kk = 0; kk < 2; kk++) {
            uint32_t ah[16], al[16], bh[8], bl[8];
            #pragma unroll
            for (int mi = 0; mi < 4; mi++) {
                ldsm4(ah + mi * 4, base +        aOff[mi] + kk * 32);
                ldsm4(al + mi * 4, base + MATB + aOff[mi] + kk * 32);
            }
            #pragma unroll
            for (int j = 0; j < 2; j++) {
                ldsm4(bh + j * 4, base + 2 * MATB + bOff[j] + kk * 32);
                ldsm4(bl + j * 4, base + 3 * MATB + bOff[j] + kk * 32);
            }
            #pragma unroll
            for (int mi = 0; mi < 4; mi++)
                #pragma unroll
                for (int ni = 0; ni < 4; ni++) {
                    mma16816(acc[mi][ni], ah + mi * 4, bh + ni * 2);
                    mma16816(acc[mi][ni], ah + mi * 4, bl + ni * 2);
                    mma16816(acc[mi][ni], al + mi * 4, bh + ni * 2);
                }
        }
    }

    __syncthreads();   // last stage fully consumed before epilogue reuses nothing; keeps warps together

    // epilogue: d0,d1=(r,c..c+1), d2,d3=(r+8,c..c+1)
    const int r  = lane >> 2;
    const int cp = (lane & 3) * 2;
    #pragma unroll
    for (int mi = 0; mi < 4; mi++) {
        #pragma unroll
        for (int ni = 0; ni < 4; ni++) {
            int col  = n0 + wn * 32 + ni * 8 + cp;
            int row0 = m0 + wm * 64 + mi * 16 + r;
            #pragma unroll
            for (int hh = 0; hh < 2; hh++) {
                int row = row0 + hh * 8;
                float v0 = acc[mi][ni][hh * 2];
                float v1 = acc[mi][ni][hh * 2 + 1];
                if (BIAS) { v0 += bias[col]; v1 += bias[col + 1]; }
                if (RELU) { v0 = fmaxf(v0, 0.0f); v1 = fmaxf(v1, 0.0f); }
                if (RESID) {
                    float2 rr = *(const float2*)(resid + (size_t)row * N + col);
                    v0 += rr.x; v1 += rr.y;
                }
                *(float2*)(C + (size_t)row * N + col) = make_float2(v0, v1);
                if (OSPLIT) {
                    *(uint32_t*)(Ohi + (size_t)row * N + col) = pack_hi2(v0, v1);
                    *(uint32_t*)(Olo + (size_t)row * N + col) = pack_lo2(v0, v1);
                }
            }
        }
    }
}

// ============================================================
// fused causal attention (reference quirks: scores = k@q^T,
// v == q, scale = E^-0.5). KQ packed [M][1024] (K 0..511, Q 512..1023).
// grid (T/8, B*H), 8 warps; warp = query row t.
// ============================================================
__global__ __launch_bounds__(256) void attn_kernel(
    const float* __restrict__ KQ, float* __restrict__ O)
{
    __shared__ float qs[128][69];                 // pad 69: conflict-free both ways
    int bh = blockIdx.y;
    int b = bh >> 3, h = bh & 7;
    int wid = threadIdx.x >> 5, lane = threadIdx.x & 31;
    int t = blockIdx.x * 8 + wid;
    const float scale = 0.044194173824159216f;    // 512^-0.5
    size_t kbase = ((size_t)(b * Tq + t)) * 1024 + h * HDq;
    float k0 = KQ[kbase + lane] * scale;
    float k1 = KQ[kbase + lane + 32] * scale;
    float m = -1e30f, l = 0.0f, a0 = 0.0f, a1 = 0.0f;
    int tmax = blockIdx.x * 8 + 7;

    for (int s0 = 0; s0 <= tmax; s0 += 128) {
        #pragma unroll
        for (int it = 0; it < 8; it++) {
            int idx = it * 256 + threadIdx.x;
            int rr = idx >> 4, d4 = (idx & 15) * 4;
            float4 v = *(const float4*)&KQ[((size_t)(b * Tq + s0 + rr)) * 1024 + 512 + h * HDq + d4];
            qs[rr][d4] = v.x; qs[rr][d4+1] = v.y; qs[rr][d4+2] = v.z; qs[rr][d4+3] = v.w;
        }
        __syncthreads();

        int send = min(127, t - s0);
        int nch = (send >> 5) + 1;
        for (int c = 0; c < nch; c++) {
            int sb32 = c * 32;
            const float* qrow = qs[sb32 + lane];
            float p = 0.0f;
            #pragma unroll
            for (int d = 0; d < 32; d++)
                p = fmaf(__shfl_sync(0xffffffffu, k0, d), qrow[d], p);
            #pragma unroll
            for (int d = 0; d < 32; d++)
                p = fmaf(__shfl_sync(0xffffffffu, k1, d), qrow[d + 32], p);
            if (sb32 + lane > send) p = -1e30f;           // causal mask
            float cm = p;
            #pragma unroll
            for (int o = 16; o; o >>= 1)
                cm = fmaxf(cm, __shfl_xor_sync(0xffffffffu, cm, o));
            float mn = fmaxf(m, cm);
            float alpha = __expf(m - mn);
            float w = __expf(p - mn);
            float sw = w;
            #pragma unroll
            for (int o = 16; o; o >>= 1)
                sw += __shfl_xor_sync(0xffffffffu, sw, o);
            l = fmaf(l, alpha, sw);
            a0 *= alpha; a1 *= alpha;
            #pragma unroll 8
            for (int s2 = 0; s2 < 32; s2++) {
                float ws = __shfl_sync(0xffffffffu, w, s2);
                a0 = fmaf(ws, qs[sb32 + s2][lane], a0);
                a1 = fmaf(ws, qs[sb32 + s2][lane + 32], a1);
            }
            m = mn;
        }
        __syncthreads();
    }
    float inv = 1.0f / l;
    size_t obase = ((size_t)(b * Tq + t)) * Eq + h * HDq;
    O[obase + lane]      = a0 * inv;
    O[obase + lane + 32] = a1 * inv;
}

// ============================================================
// launch
// ============================================================
extern "C" void kernel_launch(void* const* d_in, const int* in_sizes, int n_in,
                              void* d_out, int out_size)
{
    const int*   x     = (const int*)  d_in[0];
    const float* tok   = (const float*)d_in[1];
    const float* pos   = (const float*)d_in[2];
    const float* Wk    = (const float*)d_in[3];
    const float* Wq    = (const float*)d_in[4];
    const float* Wres  = (const float*)d_in[5];
    const float* ln1g  = (const float*)d_in[6];
    const float* ln1b  = (const float*)d_in[7];
    const float* mlpW  = (const float*)d_in[8];
    const float* mlpb  = (const float*)d_in[9];
    const float* ln2g  = (const float*)d_in[10];
    const float* ln2b  = (const float*)d_in[11];
    const float* lnfg  = (const float*)d_in[12];
    const float* lnfb  = (const float*)d_in[13];
    const float* projW = (const float*)d_in[14];
    const float* projb = (const float*)d_in[15];
    float* out = (float*)d_out;

    float *h1, *h2, *kq, *mha;
    __nv_bfloat16 *h1hi, *h1lo, *hnhi, *hnlo;
    __nv_bfloat16 *wkqhi, *wkqlo, *wrhi, *wrlo, *wmhi, *wmlo, *pjhi, *pjlo;
    cudaGetSymbolAddress((void**)&h1,  g_h1);
    cudaGetSymbolAddress((void**)&h2,  g_h2);
    cudaGetSymbolAddress((void**)&kq,  g_kq);
    cudaGetSymbolAddress((void**)&mha, g_mha);
    cudaGetSymbolAddress((void**)&h1hi, g_h1hi);
    cudaGetSymbolAddress((void**)&h1lo, g_h1lo);
    cudaGetSymbolAddress((void**)&hnhi, g_hnhi);
    cudaGetSymbolAddress((void**)&hnlo, g_hnlo);
    cudaGetSymbolAddress((void**)&wkqhi, g_wkqhi);
    cudaGetSymbolAddress((void**)&wkqlo, g_wkqlo);
    cudaGetSymbolAddress((void**)&wrhi, g_wrhi);
    cudaGetSymbolAddress((void**)&wrlo, g_wrlo);
    cudaGetSymbolAddress((void**)&wmhi, g_wmhi);
    cudaGetSymbolAddress((void**)&wmlo, g_wmlo);
    cudaGetSymbolAddress((void**)&pjhi, g_pjhi);
    cudaGetSymbolAddress((void**)&pjlo, g_pjlo);

    cudaFuncSetAttribute(hgemm<false,false,false,false>, cudaFuncAttributeMaxDynamicSharedMemorySize, SMEMB);
    cudaFuncSetAttribute(hgemm<false,false,true,false>,  cudaFuncAttributeMaxDynamicSharedMemorySize, SMEMB);
    cudaFuncSetAttribute(hgemm<true,true,true,true>,     cudaFuncAttributeMaxDynamicSharedMemorySize, SMEMB);
    cudaFuncSetAttribute(hgemm<true,false,false,false>,  cudaFuncAttributeMaxDynamicSharedMemorySize, SMEMB);

    // launch 1: ALL weight prep
    prep_all<<<21120, 256>>>(Wk, Wq, Wres, mlpW, projW,
                             wkqhi, wkqlo, wrhi, wrlo, wmhi, wmlo, pjhi, pjlo);
    // launch 2: embedding
    embed_kernel<<<MROWS, 128>>>(x, tok, pos, h1, h1hi, h1lo);

    dim3 gkq(MROWS / 128, 1024 / 128);           // 32 x 8 = 256 CTAs
    dim3 ge (MROWS / 128, Eq / 128);             // 32 x 4 = 128 CTAs
    for (int i = 0; i < NBq; i++) {
        const size_t wo   = (size_t)i * Eq * Eq;
        const size_t wokq = (size_t)i * 1024 * Eq;
        ln_split_kernel<<<MROWS, 128>>>(h1, ln1g + i * Eq, ln1b + i * Eq, hnhi, hnlo);
        hgemm<false,false,false,false><<<gkq, 256, SMEMB>>>(
            hnhi, hnlo, wkqhi + wokq, wkqlo + wokq, nullptr, nullptr, kq, nullptr, nullptr, 1024);
        attn_kernel<<<dim3(Tq / 8, Bq * Hq), 256>>>(kq, mha);
        hgemm<false,false,true,false><<<ge, 256, SMEMB>>>(      // launch #6 on i=0 -> ncu target
            h1hi, h1lo, wrhi + wo, wrlo + wo, nullptr, mha, h2, nullptr, nullptr, Eq);
        ln_split_kernel<<<MROWS, 128>>>(h2, ln2g + i * Eq, ln2b + i * Eq, hnhi, hnlo);
        hgemm<true,true,true,true><<<ge, 256, SMEMB>>>(
            hnhi, hnlo, wmhi + wo, wmlo + wo, mlpb + i * Eq, h2, h1, h1hi, h1lo, Eq);
    }

    ln_split_kernel<<<MROWS, 128>>>(h1, lnfg, lnfb, hnhi, hnlo);
    hgemm<true,false,false,false><<<dim3(MROWS / 128, VOC / 128), 256, SMEMB>>>(
        hnhi, hnlo, pjhi, pjlo, projb, nullptr, out, nullptr, nullptr, VOC);
}

// round 10
// speedup vs baseline: 1.3763x; 1.3667x over previous
#include <cuda_runtime.h>
#include <cuda_bf16.h>
#include <cstdint>

// ---- problem constants ----
#define Bq   4
#define Tq   1024
#define Eq   512
#define Hq   8
#define HDq  64
#define NBq  5
#define VOC  32000
#define MROWS (Bq*Tq)          // 4096

// ---- scratch (device globals; no allocations allowed) ----
__device__ float g_h1 [MROWS*Eq];
__device__ float g_h2 [MROWS*Eq];
__device__ float g_kq [MROWS*1024];     // fused K|Q output
__device__ float g_mha[MROWS*Eq];
// activation hi/lo splits (bf16)
__device__ __nv_bfloat16 g_h1hi[MROWS*Eq], g_h1lo[MROWS*Eq];
__device__ __nv_bfloat16 g_hnhi[MROWS*Eq], g_hnlo[MROWS*Eq];
// weight hi/lo splits, transposed to [N][K=512] row-major
__device__ __nv_bfloat16 g_wkqhi[NBq*1024*Eq], g_wkqlo[NBq*1024*Eq];   // K|Q concat
__device__ __nv_bfloat16 g_wrhi[NBq*Eq*Eq], g_wrlo[NBq*Eq*Eq];
__device__ __nv_bfloat16 g_wmhi[NBq*Eq*Eq], g_wmlo[NBq*Eq*Eq];
__device__ __nv_bfloat16 g_pjhi[(size_t)Eq*VOC], g_pjlo[(size_t)Eq*VOC];

// ============================================================
// helpers
// ============================================================
__device__ __forceinline__ uint32_t smem_u32(const void* p) {
    uint32_t a;
    asm("{ .reg .u64 t; cvta.to.shared.u64 t, %1; cvt.u32.u64 %0, t; }"
        : "=r"(a) : "l"(p));
    return a;
}
__device__ __forceinline__ void ldsm4(uint32_t* r, uint32_t addr) {
    asm volatile("ldmatrix.sync.aligned.m8n8.x4.shared.b16 {%0,%1,%2,%3}, [%4];"
                 : "=r"(r[0]), "=r"(r[1]), "=r"(r[2]), "=r"(r[3]) : "r"(addr));
}
__device__ __forceinline__ void mma16816(float* c, const uint32_t* a, const uint32_t* b) {
    asm volatile(
        "mma.sync.aligned.m16n8k16.row.col.f32.bf16.bf16.f32 "
        "{%0,%1,%2,%3}, {%4,%5,%6,%7}, {%8,%9}, {%0,%1,%2,%3};"
        : "+f"(c[0]), "+f"(c[1]), "+f"(c[2]), "+f"(c[3])
        : "r"(a[0]), "r"(a[1]), "r"(a[2]), "r"(a[3]), "r"(b[0]), "r"(b[1]));
}
#define CPASYNC(dst, src) \
    asm volatile("cp.async.cg.shared.global [%0], [%1], 16;" :: "r"(dst), "l"(src))
#define CPCOMMIT() asm volatile("cp.async.commit_group;" ::: "memory")
#define CPWAIT1()  asm volatile("cp.async.wait_group 1;" ::: "memory")
#define CPWAIT0()  asm volatile("cp.async.wait_group 0;" ::: "memory")

__device__ __forceinline__ uint32_t pack_hi2(float x, float y) {
    __nv_bfloat16 hx = __float2bfloat16(x), hy = __float2bfloat16(y);
    return (uint32_t)__bfloat16_as_ushort(hx) | ((uint32_t)__bfloat16_as_ushort(hy) << 16);
}
__device__ __forceinline__ uint32_t pack_lo2(float x, float y) {
    __nv_bfloat16 hx = __float2bfloat16(x), hy = __float2bfloat16(y);
    __nv_bfloat16 lx = __float2bfloat16(x - __bfloat162float(hx));
    __nv_bfloat16 ly = __float2bfloat16(y - __bfloat162float(hy));
    return (uint32_t)__bfloat16_as_ushort(lx) | ((uint32_t)__bfloat16_as_ushort(ly) << 16);
}

// ============================================================
// prep_all: ALL weight prep in ONE launch (32x32 transpose-split tiles)
// ============================================================
__global__ __launch_bounds__(256) void prep_all(
    const float* __restrict__ Wk, const float* __restrict__ Wq,
    const float* __restrict__ Wres, const float* __restrict__ mlpW,
    const float* __restrict__ projW,
    __nv_bfloat16* __restrict__ kqhi, __nv_bfloat16* __restrict__ kqlo,
    __nv_bfloat16* __restrict__ rhi,  __nv_bfloat16* __restrict__ rlo,
    __nv_bfloat16* __restrict__ mhi,  __nv_bfloat16* __restrict__ mlo,
    __nv_bfloat16* __restrict__ phi,  __nv_bfloat16* __restrict__ plo)
{
    __shared__ float t[32][33];
    int j = blockIdx.x;
    const float* src; int rs; size_t ibase, obase;
    __nv_bfloat16 *oh, *ol;

    if (j < 2560) {                       // Wk / Wq: [nbh][e][hd] -> [nb][1024][512]
        int q = (j >= 1280);
        int u = j - q * 1280;
        int nbh = u >> 5, tt = u & 31;
        int et = tt & 15, ht = tt >> 4;
        int nb = nbh >> 3, h = nbh & 7;
        int e0 = et * 32, hd0 = ht * 32;
        src   = q ? Wq : Wk;
        rs    = HDq;
        ibase = ((size_t)nbh * Eq + e0) * HDq + hd0;
        obase = ((size_t)nb * 1024 + q * 512 + h * HDq + hd0) * 512 + e0;
        oh = kqhi; ol = kqlo;
    } else if (j < 5120) {                // Wres / mlpW: [nb][k][n] -> [nb][512][512]
        int q = (j >= 3840);
        int u = j - 2560 - q * 1280;
        int nb = u >> 8, tt = u & 255;
        int nt = tt & 15, kt = tt >> 4;
        int n0 = nt * 32, k0 = kt * 32;
        src   = q ? mlpW : Wres;
        rs    = Eq;
        ibase = ((size_t)nb * Eq + k0) * Eq + n0;
        obase = ((size_t)nb * Eq + n0) * Eq + k0;
        oh = q ? mhi : rhi; ol = q ? mlo : rlo;
    } else {                              // projW [512][VOC] -> [VOC][512]
        int u = j - 5120;
        int nt = u % 1000, kt = u / 1000;
        int n0 = nt * 32, k0 = kt * 32;
        src   = projW;
        rs    = VOC;
        ibase = (size_t)k0 * VOC + n0;
        obase = (size_t)n0 * 512 + k0;
        oh = phi; ol = plo;
    }

    int lw = threadIdx.x >> 5, lc = threadIdx.x & 31;
    #pragma unroll
    for (int i = 0; i < 4; i++) {
        int r = lw + i * 8;
        t[r][lc] = src[ibase + (size_t)r * rs + lc];
    }
    __syncthreads();
    #pragma unroll
    for (int i = 0; i < 4; i++) {
        int c = lw + i * 8;
        float v = t[lc][c];
        __nv_bfloat16 h = __float2bfloat16(v);
        __nv_bfloat16 l = __float2bfloat16(v - __bfloat162float(h));
        size_t o = obase + (size_t)c * 512 + lc;
        oh[o] = h; ol[o] = l;
    }
}

// ============================================================
// embedding: h = tok_emb[x] + pos_emb ; also write hi/lo split
// ============================================================
__global__ void embed_kernel(const int* __restrict__ x,
                             const float* __restrict__ tok,
                             const float* __restrict__ pos,
                             float* __restrict__ h,
                             __nv_bfloat16* __restrict__ ohi,
                             __nv_bfloat16* __restrict__ olo)
{
    int row = blockIdx.x;
    int t   = row & (Tq - 1);
    int idx = x[row];
    int tid = threadIdx.x;
    float4 a = ((const float4*)(tok + (size_t)idx * Eq))[tid];
    float4 p = ((const float4*)(pos + (size_t)t   * Eq))[tid];
    float4 o; o.x = a.x+p.x; o.y = a.y+p.y; o.z = a.z+p.z; o.w = a.w+p.w;
    ((float4*)(h + (size_t)row * Eq))[tid] = o;
    size_t e = (size_t)row * Eq + tid * 4;
    *(uint2*)(ohi + e) = make_uint2(pack_hi2(o.x, o.y), pack_hi2(o.z, o.w));
    *(uint2*)(olo + e) = make_uint2(pack_lo2(o.x, o.y), pack_lo2(o.z, o.w));
}

// ============================================================
// layernorm -> hi/lo bf16 split
// ============================================================
__global__ void ln_split_kernel(const float* __restrict__ in,
                                const float* __restrict__ g,
                                const float* __restrict__ b,
                                __nv_bfloat16* __restrict__ ohi,
                                __nv_bfloat16* __restrict__ olo)
{
    int row = blockIdx.x, tid = threadIdx.x;
    float4 v = ((const float4*)(in + (size_t)row * Eq))[tid];
    float s  = v.x + v.y + v.z + v.w;
    float sq = v.x*v.x + v.y*v.y + v.z*v.z + v.w*v.w;
    #pragma unroll
    for (int o = 16; o; o >>= 1) {
        s  += __shfl_xor_sync(0xffffffffu, s,  o);
        sq += __shfl_xor_sync(0xffffffffu, sq, o);
    }
    __shared__ float sm1[4], sm2[4];
    int wid = tid >> 5, lane = tid & 31;
    if (lane == 0) { sm1[wid] = s; sm2[wid] = sq; }
    __syncthreads();
    s  = sm1[0] + sm1[1] + sm1[2] + sm1[3];
    sq = sm2[0] + sm2[1] + sm2[2] + sm2[3];
    float mu   = s * (1.0f / Eq);
    float var  = sq * (1.0f / Eq) - mu * mu;
    float rstd = rsqrtf(var + 1e-5f);
    float4 gv = ((const float4*)g)[tid];
    float4 bv = ((const float4*)b)[tid];
    float4 o;
    o.x = (v.x - mu) * rstd * gv.x + bv.x;
    o.y = (v.y - mu) * rstd * gv.y + bv.y;
    o.z = (v.z - mu) * rstd * gv.z + bv.z;
    o.w = (v.w - mu) * rstd * gv.w + bv.w;
    size_t e = (size_t)row * Eq + tid * 4;
    *(uint2*)(ohi + e) = make_uint2(pack_hi2(o.x, o.y), pack_hi2(o.z, o.w));
    *(uint2*)(olo + e) = make_uint2(pack_lo2(o.x, o.y), pack_lo2(o.z, o.w));
}

// ============================================================
// bf16x3 HMMA GEMM: C[M,N] = A[M,512] @ W[512,N]
// acc += Ahi*Bhi + Ahi*Blo + Alo*Bhi  (fp32 accumulate)
// 128x128x32 tile, 256 thr = 8 warps (2m x 4n), warp 64x32.
// 2-stage cp.async; XOR-swizzled 64B rows (no padding) ->
// 64KB smem total -> 3 CTAs/SM for latency hiding.
// swizzle: physical 16B chunk = logical chunk ^ ((row>>1)&3)
// ============================================================
#define MATB   8192                     // 128 rows * 64B
#define STAGEB (4 * MATB)               // 32768
#define SMEMB  (2 * STAGEB)             // 65536

template<bool BIAS, bool RELU, bool RESID, bool OSPLIT>
__global__ __launch_bounds__(256) void hgemm(
    const __nv_bfloat16* __restrict__ Ahi, const __nv_bfloat16* __restrict__ Alo,
    const __nv_bfloat16* __restrict__ Bhi, const __nv_bfloat16* __restrict__ Blo,
    const float* __restrict__ bias, const float* __restrict__ resid,
    float* __restrict__ C,
    __nv_bfloat16* __restrict__ Ohi, __nv_bfloat16* __restrict__ Olo,
    int N)
{
    extern __shared__ char dsm[];
    const uint32_t sb = smem_u32(dsm);
    const int tid = threadIdx.x;
    const int wid = tid >> 5, lane = tid & 31;
    const int wm = wid & 1, wn = wid >> 1;
    const int m0 = blockIdx.x * 128, n0 = blockIdx.y * 128;

    // ldmatrix per-lane smem offsets (swizzled)
    uint32_t aOff[4], bOff[2];
    {
        int ml = lane >> 3, r8 = lane & 7;
        int ar  = (ml & 1) * 8 + r8;
        int ac2 = ((ml >> 1) * 8) * 2;            // col bytes: 0 or 16
        #pragma unroll
        for (int mi = 0; mi < 4; mi++) {
            int row = wm * 64 + mi * 16 + ar;
            aOff[mi] = (uint32_t)(row * 64 + (ac2 ^ (((row >> 1) & 3) << 4)));
        }
        int br  = (ml >> 1) * 8 + r8;
        int bc2 = ((ml & 1) * 8) * 2;
        #pragma unroll
        for (int j = 0; j < 2; j++) {
            int row = wn * 32 + j * 16 + br;
            bOff[j] = (uint32_t)(row * 64 + (bc2 ^ (((row >> 1) & 3) << 4)));
        }
    }

    auto loadStage = [&](int s) {
        uint32_t base = sb + (s & 1) * STAGEB;
        #pragma unroll
        for (int i = 0; i < 2; i++) {
            int idx = tid + i * 256;
            int row = idx >> 2, ch = idx & 3;
            uint32_t doff = (uint32_t)(row * 64 + ((ch ^ ((row >> 1) & 3)) << 4));
            size_t ga = (size_t)(m0 + row) * 512 + s * 32 + ch * 8;
            size_t gb = (size_t)(n0 + row) * 512 + s * 32 + ch * 8;
            CPASYNC(base +            doff, Ahi + ga);
            CPASYNC(base + MATB     + doff, Alo + ga);
            CPASYNC(base + 2 * MATB + doff, Bhi + gb);
            CPASYNC(base + 3 * MATB + doff, Blo + gb);
        }
    };

    float acc[4][4][4];
    #pragma unroll
    for (int i = 0; i < 4; i++)
        #pragma unroll
        for (int j = 0; j < 4; j++)
            #pragma unroll
            for (int q = 0; q < 4; q++) acc[i][j][q] = 0.0f;

    loadStage(0); CPCOMMIT();

    for (int s = 0; s < 16; s++) {
        if (s + 1 < 16) { loadStage(s + 1); CPCOMMIT(); CPWAIT1(); }
        else            { CPWAIT0(); }
        __syncthreads();                 // stage s visible to all warps
        uint32_t base = sb + (s & 1) * STAGEB;
        #pragma unroll
        for (int kk = 0; kk < 2; kk++) {
            uint32_t kx = (uint32_t)(kk << 5);    // +32B col == XOR (disjoint bit)
            uint32_t ah[16], al[16], bh[8], bl[8];
            #pragma unroll
            for (int mi = 0; mi < 4; mi++) {
                ldsm4(ah + mi * 4, base +        (aOff[mi] ^ kx));
                ldsm4(al + mi * 4, base + MATB + (aOff[mi] ^ kx));
            }
            #pragma unroll
            for (int j = 0; j < 2; j++) {
                ldsm4(bh + j * 4, base + 2 * MATB + (bOff[j] ^ kx));
                ldsm4(bl + j * 4, base + 3 * MATB + (bOff[j] ^ kx));
            }
            #pragma unroll
            for (int mi = 0; mi < 4; mi++)
                #pragma unroll
                for (int ni = 0; ni < 4; ni++) {
                    mma16816(acc[mi][ni], ah + mi * 4, bh + ni * 2);
                    mma16816(acc[mi][ni], ah + mi * 4, bl + ni * 2);
                    mma16816(acc[mi][ni], al + mi * 4, bh + ni * 2);
                }
        }
        __syncthreads();                 // all warps done with stage s buffer
    }

    // epilogue
    const int r  = lane >> 2;
    const int cp = (lane & 3) * 2;
    #pragma unroll
    for (int mi = 0; mi < 4; mi++) {
        #pragma unroll
        for (int ni = 0; ni < 4; ni++) {
            int col  = n0 + wn * 32 + ni * 8 + cp;
            int row0 = m0 + wm * 64 + mi * 16 + r;
            #pragma unroll
            for (int hh = 0; hh < 2; hh++) {
                int row = row0 + hh * 8;
                float v0 = acc[mi][ni][hh * 2];
                float v1 = acc[mi][ni][hh * 2 + 1];
                if (BIAS) { v0 += bias[col]; v1 += bias[col + 1]; }
                if (RELU) { v0 = fmaxf(v0, 0.0f); v1 = fmaxf(v1, 0.0f); }
                if (RESID) {
                    float2 rr = *(const float2*)(resid + (size_t)row * N + col);
                    v0 += rr.x; v1 += rr.y;
                }
                *(float2*)(C + (size_t)row * N + col) = make_float2(v0, v1);
                if (OSPLIT) {
                    *(uint32_t*)(Ohi + (size_t)row * N + col) = pack_hi2(v0, v1);
                    *(uint32_t*)(Olo + (size_t)row * N + col) = pack_lo2(v0, v1);
                }
            }
        }
    }
}

// ============================================================
// fused causal attention (quirks: scores = k[t]@q[s], v == q,
// scale = E^-0.5). KQ packed [M][1024] (K 0..511, Q 512..1023).
// No-max softmax (scores are tiny; exp cannot overflow fp32).
// Lane-parallel: lane owns score s = chunk+lane; k in registers;
// q tile stored as float2 (d, d+32) pairs for vector LDS.
// grid (T/8, B*H), 8 warps; warp = query row t.
// ============================================================
__global__ __launch_bounds__(256) void attn_kernel(
    const float* __restrict__ KQ, float* __restrict__ O)
{
    __shared__ float2 qs2[128][34];               // stride 68 words: conflict-free
    int bh = blockIdx.y;
    int b = bh >> 3, h = bh & 7;
    int wid = threadIdx.x >> 5, lane = threadIdx.x & 31;
    int t = blockIdx.x * 8 + wid;
    const float scale = 0.044194173824159216f;    // 512^-0.5

    // k for this query row, broadcast into registers (scaled)
    float kreg[64];
    {
        const float* kp = KQ + ((size_t)(b * Tq + t)) * 1024 + h * HDq;
        #pragma unroll
        for (int i = 0; i < 16; i++) {
            float4 v = *(const float4*)(kp + i * 4);
            kreg[i*4+0] = v.x * scale; kreg[i*4+1] = v.y * scale;
            kreg[i*4+2] = v.z * scale; kreg[i*4+3] = v.w * scale;
        }
    }

    float a0e = 0.f, a0o = 0.f, a1e = 0.f, a1o = 0.f, l = 0.f;
    int tmax = blockIdx.x * 8 + 7;

    for (int s0 = 0; s0 <= tmax; s0 += 128) {
        // load q rows s0..s0+127 as (d, d+32) float2 pairs
        #pragma unroll
        for (int it = 0; it < 4; it++) {
            int idx = it * 256 + threadIdx.x;
            int row = idx >> 3, jj = idx & 7, c = jj * 4;
            const float* qp = KQ + (size_t)(b * Tq + s0 + row) * 1024 + 512 + h * HDq;
            float4 lo = *(const float4*)(qp + c);
            float4 hi = *(const float4*)(qp + c + 32);
            *(float4*)&qs2[row][c]     = make_float4(lo.x, hi.x, lo.y, hi.y);
            *(float4*)&qs2[row][c + 2] = make_float4(lo.z, hi.z, lo.w, hi.w);
        }
        __syncthreads();

        int send = min(127, t - s0);
        int nch = (send >> 5) + 1;
        for (int c = 0; c < nch; c++) {
            int sb32 = c * 32;
            int srow = sb32 + lane;
            const float2* qr = qs2[srow];
            float p0 = 0.f, p1 = 0.f, p2 = 0.f, p3 = 0.f;
            #pragma unroll
            for (int d2 = 0; d2 < 32; d2 += 4) {
                float4 A = *(const float4*)&qr[d2];       // q[d2],q[d2+32],q[d2+1],q[d2+33]
                float4 Bv = *(const float4*)&qr[d2 + 2];
                p0 = fmaf(kreg[d2],      A.x,  p0);
                p1 = fmaf(kreg[d2 + 32], A.y,  p1);
                p2 = fmaf(kreg[d2 + 1],  A.z,  p2);
                p3 = fmaf(kreg[d2 + 33], A.w,  p3);
                p0 = fmaf(kreg[d2 + 2],  Bv.x, p0);
                p1 = fmaf(kreg[d2 + 34], Bv.y, p1);
                p2 = fmaf(kreg[d2 + 3],  Bv.z, p2);
                p3 = fmaf(kreg[d2 + 35], Bv.w, p3);
            }
            float p = (p0 + p1) + (p2 + p3);
            float w = (srow <= send) ? __expf(p) : 0.0f;
            l += w;
            #pragma unroll
            for (int s2 = 0; s2 < 32; s2 += 2) {
                float w0 = __shfl_sync(0xffffffffu, w, s2);
                float w1 = __shfl_sync(0xffffffffu, w, s2 + 1);
                float2 q0 = qs2[sb32 + s2][lane];
                float2 q1 = qs2[sb32 + s2 + 1][lane];
                a0e = fmaf(w0, q0.x, a0e); a1e = fmaf(w0, q0.y, a1e);
                a0o = fmaf(w1, q1.x, a0o); a1o = fmaf(w1, q1.y, a1o);
            }
        }
        __syncthreads();
    }

    float lt = l;
    #pragma unroll
    for (int o = 16; o; o >>= 1)
        lt += __shfl_xor_sync(0xffffffffu, lt, o);
    float inv = 1.0f / lt;
    size_t obase = ((size_t)(b * Tq + t)) * Eq + h * HDq;
    O[obase + lane]      = (a0e + a0o) * inv;
    O[obase + lane + 32] = (a1e + a1o) * inv;
}

// ============================================================
// launch
// ============================================================
extern "C" void kernel_launch(void* const* d_in, const int* in_sizes, int n_in,
                              void* d_out, int out_size)
{
    const int*   x     = (const int*)  d_in[0];
    const float* tok   = (const float*)d_in[1];
    const float* pos   = (const float*)d_in[2];
    const float* Wk    = (const float*)d_in[3];
    const float* Wq    = (const float*)d_in[4];
    const float* Wres  = (const float*)d_in[5];
    const float* ln1g  = (const float*)d_in[6];
    const float* ln1b  = (const float*)d_in[7];
    const float* mlpW  = (const float*)d_in[8];
    const float* mlpb  = (const float*)d_in[9];
    const float* ln2g  = (const float*)d_in[10];
    const float* ln2b  = (const float*)d_in[11];
    const float* lnfg  = (const float*)d_in[12];
    const float* lnfb  = (const float*)d_in[13];
    const float* projW = (const float*)d_in[14];
    const float* projb = (const float*)d_in[15];
    float* out = (float*)d_out;

    float *h1, *h2, *kq, *mha;
    __nv_bfloat16 *h1hi, *h1lo, *hnhi, *hnlo;
    __nv_bfloat16 *wkqhi, *wkqlo, *wrhi, *wrlo, *wmhi, *wmlo, *pjhi, *pjlo;
    cudaGetSymbolAddress((void**)&h1,  g_h1);
    cudaGetSymbolAddress((void**)&h2,  g_h2);
    cudaGetSymbolAddress((void**)&kq,  g_kq);
    cudaGetSymbolAddress((void**)&mha, g_mha);
    cudaGetSymbolAddress((void**)&h1hi, g_h1hi);
    cudaGetSymbolAddress((void**)&h1lo, g_h1lo);
    cudaGetSymbolAddress((void**)&hnhi, g_hnhi);
    cudaGetSymbolAddress((void**)&hnlo, g_hnlo);
    cudaGetSymbolAddress((void**)&wkqhi, g_wkqhi);
    cudaGetSymbolAddress((void**)&wkqlo, g_wkqlo);
    cudaGetSymbolAddress((void**)&wrhi, g_wrhi);
    cudaGetSymbolAddress((void**)&wrlo, g_wrlo);
    cudaGetSymbolAddress((void**)&wmhi, g_wmhi);
    cudaGetSymbolAddress((void**)&wmlo, g_wmlo);
    cudaGetSymbolAddress((void**)&pjhi, g_pjhi);
    cudaGetSymbolAddress((void**)&pjlo, g_pjlo);

    cudaFuncSetAttribute(hgemm<false,false,false,false>, cudaFuncAttributeMaxDynamicSharedMemorySize, SMEMB);
    cudaFuncSetAttribute(hgemm<false,false,true,false>,  cudaFuncAttributeMaxDynamicSharedMemorySize, SMEMB);
    cudaFuncSetAttribute(hgemm<true,true,true,true>,     cudaFuncAttributeMaxDynamicSharedMemorySize, SMEMB);
    cudaFuncSetAttribute(hgemm<true,false,false,false>,  cudaFuncAttributeMaxDynamicSharedMemorySize, SMEMB);

    prep_all<<<21120, 256>>>(Wk, Wq, Wres, mlpW, projW,
                             wkqhi, wkqlo, wrhi, wrlo, wmhi, wmlo, pjhi, pjlo);
    embed_kernel<<<MROWS, 128>>>(x, tok, pos, h1, h1hi, h1lo);

    dim3 gkq(MROWS / 128, 1024 / 128);           // 32 x 8 = 256 CTAs
    dim3 ge (MROWS / 128, Eq / 128);             // 32 x 4 = 128 CTAs
    for (int i = 0; i < NBq; i++) {
        const size_t wo   = (size_t)i * Eq * Eq;
        const size_t wokq = (size_t)i * 1024 * Eq;
        ln_split_kernel<<<MROWS, 128>>>(h1, ln1g + i * Eq, ln1b + i * Eq, hnhi, hnlo);
        hgemm<false,false,false,false><<<gkq, 256, SMEMB>>>(
            hnhi, hnlo, wkqhi + wokq, wkqlo + wokq, nullptr, nullptr, kq, nullptr, nullptr, 1024);
        attn_kernel<<<dim3(Tq / 8, Bq * Hq), 256>>>(kq, mha);
        hgemm<false,false,true,false><<<ge, 256, SMEMB>>>(
            h1hi, h1lo, wrhi + wo, wrlo + wo, nullptr, mha, h2, nullptr, nullptr, Eq);
        ln_split_kernel<<<MROWS, 128>>>(h2, ln2g + i * Eq, ln2b + i * Eq, hnhi, hnlo);
        hgemm<true,true,true,true><<<ge, 256, SMEMB>>>(
            hnhi, hnlo, wmhi + wo, wmlo + wo, mlpb + i * Eq, h2, h1, h1hi, h1lo, Eq);
    }

    ln_split_kernel<<<MROWS, 128>>>(h1, lnfg, lnfb, hnhi, hnlo);
    hgemm<true,false,false,false><<<dim3(MROWS / 128, VOC / 128), 256, SMEMB>>>(
        hnhi, hnlo, pjhi, pjlo, projb, nullptr, out, nullptr, nullptr, VOC);
}

// round 12
// speedup vs baseline: 1.3848x; 1.0062x over previous
#include <cuda_runtime.h>
#include <cuda_bf16.h>
#include <cstdint>

// ---- problem constants ----
#define Bq   4
#define Tq   1024
#define Eq   512
#define Hq   8
#define HDq  64
#define NBq  5
#define VOC  32000
#define MROWS (Bq*Tq)          // 4096

// ---- scratch (device globals; no allocations allowed) ----
__device__ float g_h1 [MROWS*Eq];
__device__ float g_h2 [MROWS*Eq];
__device__ float g_kq [MROWS*1024];     // fused K|Q output
__device__ float g_mha[MROWS*Eq];
// activation hi/lo splits (bf16)
__device__ __nv_bfloat16 g_h1hi[MROWS*Eq], g_h1lo[MROWS*Eq];
__device__ __nv_bfloat16 g_hnhi[MROWS*Eq], g_hnlo[MROWS*Eq];
// weight hi/lo splits, transposed to [N][K=512] row-major
__device__ __nv_bfloat16 g_wkqhi[NBq*1024*Eq], g_wkqlo[NBq*1024*Eq];   // K|Q concat
__device__ __nv_bfloat16 g_wrhi[NBq*Eq*Eq], g_wrlo[NBq*Eq*Eq];
__device__ __nv_bfloat16 g_wmhi[NBq*Eq*Eq], g_wmlo[NBq*Eq*Eq];
__device__ __nv_bfloat16 g_pjhi[(size_t)Eq*VOC], g_pjlo[(size_t)Eq*VOC];

// ============================================================
// helpers
// ============================================================
__device__ __forceinline__ uint32_t smem_u32(const void* p) {
    uint32_t a;
    asm("{ .reg .u64 t; cvta.to.shared.u64 t, %1; cvt.u32.u64 %0, t; }"
        : "=r"(a) : "l"(p));
    return a;
}
__device__ __forceinline__ void ldsm4(uint32_t* r, uint32_t addr) {
    asm volatile("ldmatrix.sync.aligned.m8n8.x4.shared.b16 {%0,%1,%2,%3}, [%4];"
                 : "=r"(r[0]), "=r"(r[1]), "=r"(r[2]), "=r"(r[3]) : "r"(addr));
}
__device__ __forceinline__ void mma16816(float* c, const uint32_t* a, const uint32_t* b) {
    asm volatile(
        "mma.sync.aligned.m16n8k16.row.col.f32.bf16.bf16.f32 "
        "{%0,%1,%2,%3}, {%4,%5,%6,%7}, {%8,%9}, {%0,%1,%2,%3};"
        : "+f"(c[0]), "+f"(c[1]), "+f"(c[2]), "+f"(c[3])
        : "r"(a[0]), "r"(a[1]), "r"(a[2]), "r"(a[3]), "r"(b[0]), "r"(b[1]));
}
#define CPASYNC(dst, src) \
    asm volatile("cp.async.cg.shared.global [%0], [%1], 16;" :: "r"(dst), "l"(src))
#define CPCOMMIT() asm volatile("cp.async.commit_group;" ::: "memory")
#define CPWAIT1()  asm volatile("cp.async.wait_group 1;" ::: "memory")
#define CPWAIT0()  asm volatile("cp.async.wait_group 0;" ::: "memory")

__device__ __forceinline__ uint32_t pack_hi2(float x, float y) {
    __nv_bfloat16 hx = __float2bfloat16(x), hy = __float2bfloat16(y);
    return (uint32_t)__bfloat16_as_ushort(hx) | ((uint32_t)__bfloat16_as_ushort(hy) << 16);
}
__device__ __forceinline__ uint32_t pack_lo2(float x, float y) {
    __nv_bfloat16 hx = __float2bfloat16(x), hy = __float2bfloat16(y);
    __nv_bfloat16 lx = __float2bfloat16(x - __bfloat162float(hx));
    __nv_bfloat16 ly = __float2bfloat16(y - __bfloat162float(hy));
    return (uint32_t)__bfloat16_as_ushort(lx) | ((uint32_t)__bfloat16_as_ushort(ly) << 16);
}

// ============================================================
// prep_all: ALL weight prep in ONE launch (32x32 transpose-split tiles)
// ============================================================
__global__ __launch_bounds__(256) void prep_all(
    const float* __restrict__ Wk, const float* __restrict__ Wq,
    const float* __restrict__ Wres, const float* __restrict__ mlpW,
    const float* __restrict__ projW,
    __nv_bfloat16* __restrict__ kqhi, __nv_bfloat16* __restrict__ kqlo,
    __nv_bfloat16* __restrict__ rhi,  __nv_bfloat16* __restrict__ rlo,
    __nv_bfloat16* __restrict__ mhi,  __nv_bfloat16* __restrict__ mlo,
    __nv_bfloat16* __restrict__ phi,  __nv_bfloat16* __restrict__ plo)
{
    __shared__ float t[32][33];
    int j = blockIdx.x;
    const float* src; int rs; size_t ibase, obase;
    __nv_bfloat16 *oh, *ol;

    if (j < 2560) {                       // Wk / Wq: [nbh][e][hd] -> [nb][1024][512]
        int q = (j >= 1280);
        int u = j - q * 1280;
        int nbh = u >> 5, tt = u & 31;
        int et = tt & 15, ht = tt >> 4;
        int nb = nbh >> 3, h = nbh & 7;
        int e0 = et * 32, hd0 = ht * 32;
        src   = q ? Wq : Wk;
        rs    = HDq;
        ibase = ((size_t)nbh * Eq + e0) * HDq + hd0;
        obase = ((size_t)nb * 1024 + q * 512 + h * HDq + hd0) * 512 + e0;
        oh = kqhi; ol = kqlo;
    } else if (j < 5120) {                // Wres / mlpW: [nb][k][n] -> [nb][512][512]
        int q = (j >= 3840);
        int u = j - 2560 - q * 1280;
        int nb = u >> 8, tt = u & 255;
        int nt = tt & 15, kt = tt >> 4;
        int n0 = nt * 32, k0 = kt * 32;
        src   = q ? mlpW : Wres;
        rs    = Eq;
        ibase = ((size_t)nb * Eq + k0) * Eq + n0;
        obase = ((size_t)nb * Eq + n0) * Eq + k0;
        oh = q ? mhi : rhi; ol = q ? mlo : rlo;
    } else {                              // projW [512][VOC] -> [VOC][512]
        int u = j - 5120;
        int nt = u % 1000, kt = u / 1000;
        int n0 = nt * 32, k0 = kt * 32;
        src   = projW;
        rs    = VOC;
        ibase = (size_t)k0 * VOC + n0;
        obase = (size_t)n0 * 512 + k0;
        oh = phi; ol = plo;
    }

    int lw = threadIdx.x >> 5, lc = threadIdx.x & 31;
    #pragma unroll
    for (int i = 0; i < 4; i++) {
        int r = lw + i * 8;
        t[r][lc] = src[ibase + (size_t)r * rs + lc];
    }
    __syncthreads();
    #pragma unroll
    for (int i = 0; i < 4; i++) {
        int c = lw + i * 8;
        float v = t[lc][c];
        __nv_bfloat16 h = __float2bfloat16(v);
        __nv_bfloat16 l = __float2bfloat16(v - __bfloat162float(h));
        size_t o = obase + (size_t)c * 512 + lc;
        oh[o] = h; ol[o] = l;
    }
}

// ============================================================
// embedding: h = tok_emb[x] + pos_emb ; also write hi/lo split
// ============================================================
__global__ void embed_kernel(const int* __restrict__ x,
                             const float* __restrict__ tok,
                             const float* __restrict__ pos,
                             float* __restrict__ h,
                             __nv_bfloat16* __restrict__ ohi,
                             __nv_bfloat16* __restrict__ olo)
{
    int row = blockIdx.x;
    int t   = row & (Tq - 1);
    int idx = x[row];
    int tid = threadIdx.x;
    float4 a = ((const float4*)(tok + (size_t)idx * Eq))[tid];
    float4 p = ((const float4*)(pos + (size_t)t   * Eq))[tid];
    float4 o; o.x = a.x+p.x; o.y = a.y+p.y; o.z = a.z+p.z; o.w = a.w+p.w;
    ((float4*)(h + (size_t)row * Eq))[tid] = o;
    size_t e = (size_t)row * Eq + tid * 4;
    *(uint2*)(ohi + e) = make_uint2(pack_hi2(o.x, o.y), pack_hi2(o.z, o.w));
    *(uint2*)(olo + e) = make_uint2(pack_lo2(o.x, o.y), pack_lo2(o.z, o.w));
}

// ============================================================
// layernorm -> hi/lo bf16 split
// ============================================================
__global__ void ln_split_kernel(const float* __restrict__ in,
                                const float* __restrict__ g,
                                const float* __restrict__ b,
                                __nv_bfloat16* __restrict__ ohi,
                                __nv_bfloat16* __restrict__ olo)
{
    int row = blockIdx.x, tid = threadIdx.x;
    float4 v = ((const float4*)(in + (size_t)row * Eq))[tid];
    float s  = v.x + v.y + v.z + v.w;
    float sq = v.x*v.x + v.y*v.y + v.z*v.z + v.w*v.w;
    #pragma unroll
    for (int o = 16; o; o >>= 1) {
        s  += __shfl_xor_sync(0xffffffffu, s,  o);
        sq += __shfl_xor_sync(0xffffffffu, sq, o);
    }
    __shared__ float sm1[4], sm2[4];
    int wid = tid >> 5, lane = tid & 31;
    if (lane == 0) { sm1[wid] = s; sm2[wid] = sq; }
    __syncthreads();
    s  = sm1[0] + sm1[1] + sm1[2] + sm1[3];
    sq = sm2[0] + sm2[1] + sm2[2] + sm2[3];
    float mu   = s * (1.0f / Eq);
    float var  = sq * (1.0f / Eq) - mu * mu;
    float rstd = rsqrtf(var + 1e-5f);
    float4 gv = ((const float4*)g)[tid];
    float4 bv = ((const float4*)b)[tid];
    float4 o;
    o.x = (v.x - mu) * rstd * gv.x + bv.x;
    o.y = (v.y - mu) * rstd * gv.y + bv.y;
    o.z = (v.z - mu) * rstd * gv.z + bv.z;
    o.w = (v.w - mu) * rstd * gv.w + bv.w;
    size_t e = (size_t)row * Eq + tid * 4;
    *(uint2*)(ohi + e) = make_uint2(pack_hi2(o.x, o.y), pack_hi2(o.z, o.w));
    *(uint2*)(olo + e) = make_uint2(pack_lo2(o.x, o.y), pack_lo2(o.z, o.w));
}

// ============================================================
// bf16x3 HMMA GEMM: C[M,N] = A[M,512] @ W[512,N]
// acc += Ahi*Bhi + Ahi*Blo + Alo*Bhi  (fp32 accumulate)
// 128x64x32 tile, 256 thr = 8 warps (4m x 2n), warp 32x32.
// 2-stage cp.async; XOR-swizzled 64B rows -> 48KB smem, and
// __launch_bounds__(256,3) -> 3 CTAs/SM for latency hiding.
// ============================================================
#define A_HI 0
#define A_LO 8192
#define B_HI 16384
#define B_LO 20480
#define STAGEB 24576
#define SMEMB  (2 * STAGEB)             // 49152

template<bool BIAS, bool RELU, bool RESID, bool OSPLIT>
__global__ __launch_bounds__(256, 3) void hgemm(
    const __nv_bfloat16* __restrict__ Ahi, const __nv_bfloat16* __restrict__ Alo,
    const __nv_bfloat16* __restrict__ Bhi, const __nv_bfloat16* __restrict__ Blo,
    const float* __restrict__ bias, const float* __restrict__ resid,
    float* __restrict__ C,
    __nv_bfloat16* __restrict__ Ohi, __nv_bfloat16* __restrict__ Olo,
    int N)
{
    extern __shared__ char dsm[];
    const uint32_t sb = smem_u32(dsm);
    const int tid = threadIdx.x;
    const int wid = tid >> 5, lane = tid & 31;
    const int wm = wid & 3, wn = wid >> 2;
    const int m0 = blockIdx.x * 128, n0 = blockIdx.y * 64;

    // ldmatrix per-lane smem offsets (swizzled)
    uint32_t aOff[2], bOff[2];
    {
        int ml = lane >> 3, r8 = lane & 7;
        int ar  = (ml & 1) * 8 + r8;
        int ac2 = ((ml >> 1) * 8) * 2;            // col bytes: 0 or 16
        #pragma unroll
        for (int mi = 0; mi < 2; mi++) {
            int row = wm * 32 + mi * 16 + ar;
            aOff[mi] = (uint32_t)(row * 64 + (ac2 ^ (((row >> 1) & 3) << 4)));
        }
        int br  = (ml >> 1) * 8 + r8;
        int bc2 = ((ml & 1) * 8) * 2;
        #pragma unroll
        for (int j = 0; j < 2; j++) {
            int row = wn * 32 + j * 16 + br;
            bOff[j] = (uint32_t)(row * 64 + (bc2 ^ (((row >> 1) & 3) << 4)));
        }
    }

    auto loadStage = [&](int s) {
        uint32_t base = sb + (s & 1) * STAGEB;
        #pragma unroll
        for (int i = 0; i < 2; i++) {             // A: 512 chunks (hi+lo pairs)
            int idx = tid + i * 256;
            int row = idx >> 2, ch = idx & 3;
            uint32_t doff = (uint32_t)(row * 64 + ((ch ^ ((row >> 1) & 3)) << 4));
            size_t ga = (size_t)(m0 + row) * 512 + s * 32 + ch * 8;
            CPASYNC(base + A_HI + doff, Ahi + ga);
            CPASYNC(base + A_LO + doff, Alo + ga);
        }
        {                                          // B: 256 chunks (hi+lo pairs)
            int row = tid >> 2, ch = tid & 3;
            uint32_t doff = (uint32_t)(row * 64 + ((ch ^ ((row >> 1) & 3)) << 4));
            size_t gb = (size_t)(n0 + row) * 512 + s * 32 + ch * 8;
            CPASYNC(base + B_HI + doff, Bhi + gb);
            CPASYNC(base + B_LO + doff, Blo + gb);
        }
    };

    float acc[2][4][4];
    #pragma unroll
    for (int i = 0; i < 2; i++)
        #pragma unroll
        for (int j = 0; j < 4; j++)
            #pragma unroll
            for (int q = 0; q < 4; q++) acc[i][j][q] = 0.0f;

    loadStage(0); CPCOMMIT();

    for (int s = 0; s < 16; s++) {
        if (s + 1 < 16) { loadStage(s + 1); CPCOMMIT(); CPWAIT1(); }
        else            { CPWAIT0(); }
        __syncthreads();                 // stage s visible to all warps
        uint32_t base = sb + (s & 1) * STAGEB;
        #pragma unroll
        for (int kk = 0; kk < 2; kk++) {
            uint32_t kx = (uint32_t)(kk << 5);    // +32B col == XOR (disjoint bit)
            uint32_t ah[8], al[8], bh[8], bl[8];
            #pragma unroll
            for (int mi = 0; mi < 2; mi++) {
                ldsm4(ah + mi * 4, base + A_HI + (aOff[mi] ^ kx));
                ldsm4(al + mi * 4, base + A_LO + (aOff[mi] ^ kx));
            }
            #pragma unroll
            for (int j = 0; j < 2; j++) {
                ldsm4(bh + j * 4, base + B_HI + (bOff[j] ^ kx));
                ldsm4(bl + j * 4, base + B_LO + (bOff[j] ^ kx));
            }
            #pragma unroll
            for (int mi = 0; mi < 2; mi++)
                #pragma unroll
                for (int ni = 0; ni < 4; ni++) {
                    mma16816(acc[mi][ni], ah + mi * 4, bh + ni * 2);
                    mma16816(acc[mi][ni], ah + mi * 4, bl + ni * 2);
                    mma16816(acc[mi][ni], al + mi * 4, bh + ni * 2);
                }
        }
        __syncthreads();                 // all warps done with stage s buffer
    }

    // epilogue
    const int r  = lane >> 2;
    const int cp = (lane & 3) * 2;
    #pragma unroll
    for (int mi = 0; mi < 2; mi++) {
        #pragma unroll
        for (int ni = 0; ni < 4; ni++) {
            int col  = n0 + wn * 32 + ni * 8 + cp;
            int row0 = m0 + wm * 32 + mi * 16 + r;
            #pragma unroll
            for (int hh = 0; hh < 2; hh++) {
                int row = row0 + hh * 8;
                float v0 = acc[mi][ni][hh * 2];
                float v1 = acc[mi][ni][hh * 2 + 1];
                if (BIAS) { v0 += bias[col]; v1 += bias[col + 1]; }
                if (RELU) { v0 = fmaxf(v0, 0.0f); v1 = fmaxf(v1, 0.0f); }
                if (RESID) {
                    float2 rr = *(const float2*)(resid + (size_t)row * N + col);
                    v0 += rr.x; v1 += rr.y;
                }
                *(float2*)(C + (size_t)row * N + col) = make_float2(v0, v1);
                if (OSPLIT) {
                    *(uint32_t*)(Ohi + (size_t)row * N + col) = pack_hi2(v0, v1);
                    *(uint32_t*)(Olo + (size_t)row * N + col) = pack_lo2(v0, v1);
                }
            }
        }
    }
}

// ============================================================
// fused causal attention (quirks: scores = k[t]@q[s], v == q,
// scale = E^-0.5). KQ packed [M][1024] (K 0..511, Q 512..1023).
// No-max softmax; lane-parallel scoring; k in registers.
// grid (T/8, B*H), 8 warps; warp = query row t.
// ============================================================
__global__ __launch_bounds__(256) void attn_kernel(
    const float* __restrict__ KQ, float* __restrict__ O)
{
    __shared__ float2 qs2[128][34];               // stride 68 words: conflict-free
    int bh = blockIdx.y;
    int b = bh >> 3, h = bh & 7;
    int wid = threadIdx.x >> 5, lane = threadIdx.x & 31;
    int t = blockIdx.x * 8 + wid;
    const float scale = 0.044194173824159216f;    // 512^-0.5

    float kreg[64];
    {
        const float* kp = KQ + ((size_t)(b * Tq + t)) * 1024 + h * HDq;
        #pragma unroll
        for (int i = 0; i < 16; i++) {
            float4 v = *(const float4*)(kp + i * 4);
            kreg[i*4+0] = v.x * scale; kreg[i*4+1] = v.y * scale;
            kreg[i*4+2] = v.z * scale; kreg[i*4+3] = v.w * scale;
        }
    }

    float a0e = 0.f, a0o = 0.f, a1e = 0.f, a1o = 0.f, l = 0.f;
    int tmax = blockIdx.x * 8 + 7;

    for (int s0 = 0; s0 <= tmax; s0 += 128) {
        #pragma unroll
        for (int it = 0; it < 4; it++) {
            int idx = it * 256 + threadIdx.x;
            int row = idx >> 3, jj = idx & 7, c = jj * 4;
            const float* qp = KQ + (size_t)(b * Tq + s0 + row) * 1024 + 512 + h * HDq;
            float4 lo = *(const float4*)(qp + c);
            float4 hi = *(const float4*)(qp + c + 32);
            *(float4*)&qs2[row][c]     = make_float4(lo.x, hi.x, lo.y, hi.y);
            *(float4*)&qs2[row][c + 2] = make_float4(lo.z, hi.z, lo.w, hi.w);
        }
        __syncthreads();

        int send = min(127, t - s0);
        int nch = (send >> 5) + 1;
        for (int c = 0; c < nch; c++) {
            int sb32 = c * 32;
            int srow = sb32 + lane;
            const float2* qr = qs2[srow];
            float p0 = 0.f, p1 = 0.f, p2 = 0.f, p3 = 0.f;
            #pragma unroll
            for (int d2 = 0; d2 < 32; d2 += 4) {
                float4 A = *(const float4*)&qr[d2];
                float4 Bv = *(const float4*)&qr[d2 + 2];
                p0 = fmaf(kreg[d2],      A.x,  p0);
                p1 = fmaf(kreg[d2 + 32], A.y,  p1);
                p2 = fmaf(kreg[d2 + 1],  A.z,  p2);
                p3 = fmaf(kreg[d2 + 33], A.w,  p3);
                p0 = fmaf(kreg[d2 + 2],  Bv.x, p0);
                p1 = fmaf(kreg[d2 + 34], Bv.y, p1);
                p2 = fmaf(kreg[d2 + 3],  Bv.z, p2);
                p3 = fmaf(kreg[d2 + 35], Bv.w, p3);
            }
            float p = (p0 + p1) + (p2 + p3);
            float w = (srow <= send) ? __expf(p) : 0.0f;
            l += w;
            #pragma unroll
            for (int s2 = 0; s2 < 32; s2 += 2) {
                float w0 = __shfl_sync(0xffffffffu, w, s2);
                float w1 = __shfl_sync(0xffffffffu, w, s2 + 1);
                float2 q0 = qs2[sb32 + s2][lane];
                float2 q1 = qs2[sb32 + s2 + 1][lane];
                a0e = fmaf(w0, q0.x, a0e); a1e = fmaf(w0, q0.y, a1e);
                a0o = fmaf(w1, q1.x, a0o); a1o = fmaf(w1, q1.y, a1o);
            }
        }
        __syncthreads();
    }

    float lt = l;
    #pragma unroll
    for (int o = 16; o; o >>= 1)
        lt += __shfl_xor_sync(0xffffffffu, lt, o);
    float inv = 1.0f / lt;
    size_t obase = ((size_t)(b * Tq + t)) * Eq + h * HDq;
    O[obase + lane]      = (a0e + a0o) * inv;
    O[obase + lane + 32] = (a1e + a1o) * inv;
}

// ============================================================
// launch
// ============================================================
extern "C" void kernel_launch(void* const* d_in, const int* in_sizes, int n_in,
                              void* d_out, int out_size)
{
    const int*   x     = (const int*)  d_in[0];
    const float* tok   = (const float*)d_in[1];
    const float* pos   = (const float*)d_in[2];
    const float* Wk    = (const float*)d_in[3];
    const float* Wq    = (const float*)d_in[4];
    const float* Wres  = (const float*)d_in[5];
    const float* ln1g  = (const float*)d_in[6];
    const float* ln1b  = (const float*)d_in[7];
    const float* mlpW  = (const float*)d_in[8];
    const float* mlpb  = (const float*)d_in[9];
    const float* ln2g  = (const float*)d_in[10];
    const float* ln2b  = (const float*)d_in[11];
    const float* lnfg  = (const float*)d_in[12];
    const float* lnfb  = (const float*)d_in[13];
    const float* projW = (const float*)d_in[14];
    const float* projb = (const float*)d_in[15];
    float* out = (float*)d_out;

    float *h1, *h2, *kq, *mha;
    __nv_bfloat16 *h1hi, *h1lo, *hnhi, *hnlo;
    __nv_bfloat16 *wkqhi, *wkqlo, *wrhi, *wrlo, *wmhi, *wmlo, *pjhi, *pjlo;
    cudaGetSymbolAddress((void**)&h1,  g_h1);
    cudaGetSymbolAddress((void**)&h2,  g_h2);
    cudaGetSymbolAddress((void**)&kq,  g_kq);
    cudaGetSymbolAddress((void**)&mha, g_mha);
    cudaGetSymbolAddress((void**)&h1hi, g_h1hi);
    cudaGetSymbolAddress((void**)&h1lo, g_h1lo);
    cudaGetSymbolAddress((void**)&hnhi, g_hnhi);
    cudaGetSymbolAddress((void**)&hnlo, g_hnlo);
    cudaGetSymbolAddress((void**)&wkqhi, g_wkqhi);
    cudaGetSymbolAddress((void**)&wkqlo, g_wkqlo);
    cudaGetSymbolAddress((void**)&wrhi, g_wrhi);
    cudaGetSymbolAddress((void**)&wrlo, g_wrlo);
    cudaGetSymbolAddress((void**)&wmhi, g_wmhi);
    cudaGetSymbolAddress((void**)&wmlo, g_wmlo);
    cudaGetSymbolAddress((void**)&pjhi, g_pjhi);
    cudaGetSymbolAddress((void**)&pjlo, g_pjlo);

    cudaFuncSetAttribute(hgemm<false,false,false,false>, cudaFuncAttributeMaxDynamicSharedMemorySize, SMEMB);
    cudaFuncSetAttribute(hgemm<false,false,true,false>,  cudaFuncAttributeMaxDynamicSharedMemorySize, SMEMB);
    cudaFuncSetAttribute(hgemm<true,true,true,true>,     cudaFuncAttributeMaxDynamicSharedMemorySize, SMEMB);
    cudaFuncSetAttribute(hgemm<true,false,false,false>,  cudaFuncAttributeMaxDynamicSharedMemorySize, SMEMB);

    prep_all<<<21120, 256>>>(Wk, Wq, Wres, mlpW, projW,
                             wkqhi, wkqlo, wrhi, wrlo, wmhi, wmlo, pjhi, pjlo);
    embed_kernel<<<MROWS, 128>>>(x, tok, pos, h1, h1hi, h1lo);

    dim3 gkq(MROWS / 128, 1024 / 64);            // 32 x 16 = 512 CTAs
    dim3 ge (MROWS / 128, Eq / 64);              // 32 x 8  = 256 CTAs
    for (int i = 0; i < NBq; i++) {
        const size_t wo   = (size_t)i * Eq * Eq;
        const size_t wokq = (size_t)i * 1024 * Eq;
        ln_split_kernel<<<MROWS, 128>>>(h1, ln1g + i * Eq, ln1b + i * Eq, hnhi, hnlo);
        hgemm<false,false,false,false><<<gkq, 256, SMEMB>>>(
            hnhi, hnlo, wkqhi + wokq, wkqlo + wokq, nullptr, nullptr, kq, nullptr, nullptr, 1024);
        attn_kernel<<<dim3(Tq / 8, Bq * Hq), 256>>>(kq, mha);
        hgemm<false,false,true,false><<<ge, 256, SMEMB>>>(
            h1hi, h1lo, wrhi + wo, wrlo + wo, nullptr, mha, h2, nullptr, nullptr, Eq);
        ln_split_kernel<<<MROWS, 128>>>(h2, ln2g + i * Eq, ln2b + i * Eq, hnhi, hnlo);
        hgemm<true,true,true,true><<<ge, 256, SMEMB>>>(
            hnhi, hnlo, wmhi + wo, wmlo + wo, mlpb + i * Eq, h2, h1, h1hi, h1lo, Eq);
    }

    ln_split_kernel<<<MROWS, 128>>>(h1, lnfg, lnfb, hnhi, hnlo);
    hgemm<true,false,false,false><<<dim3(MROWS / 128, VOC / 64), 256, SMEMB>>>(
        hnhi, hnlo, pjhi, pjlo, projb, nullptr, out, nullptr, nullptr, VOC);
}